// round 2
// baseline (speedup 1.0000x reference)
#include <cuda_runtime.h>
#include <math.h>

#define B_ 128
#define S_ 256
#define E_ 300
#define H_ 300
#define G4 1200   // 4*H
#define DIV 601   // 2H+1

// ---------------- scratch (device globals; no allocations allowed) ----------
__device__ float g_mem [B_*S_*E_];          // embedded text [B,S,300]
__device__ float g_xgf [B_*S_*G4];          // fwd input gates [B,S,1200]
__device__ float g_xgb [B_*S_*G4];          // bwd input gates
__device__ float g_outf[B_*S_*H_];          // fwd LSTM outputs
__device__ float g_outb[B_*S_*H_];          // bwd LSTM outputs
__device__ float g_ivec[B_*DIV];            // attended vector [B,601]
__device__ int   g_mlen[B_], g_llen[B_], g_alen[B_];

// ---------------- K0: lengths ----------------------------------------------
__global__ void k_prep(const int* __restrict__ text,
                       const int* __restrict__ aspect,
                       const int* __restrict__ leftc) {
    int b = blockIdx.x, t = threadIdx.x;
    int c1 = __syncthreads_count(text[b*S_ + t] != 0);
    int c2 = __syncthreads_count(leftc[b*S_ + t] != 0);
    int c3 = __syncthreads_count(t < 8 && aspect[b*8 + t] != 0);
    if (t == 0) { g_mlen[b] = c1; g_llen[b] = c2; g_alen[b] = c3; }
}

// ---------------- K1: embedding gather --------------------------------------
__global__ void k_embed(const int* __restrict__ text,
                        const float* __restrict__ emb) {
    int r = blockIdx.x;                       // b*S + s
    int id = text[r];
    const float4* src = (const float4*)(emb + (size_t)id * E_);
    float4* dst = (float4*)(g_mem + (size_t)r * E_);
    int t = threadIdx.x;
    if (t < 75) dst[t] = src[t];              // 300 floats = 75 float4
}

// ---------------- K2: xg GEMM  C[M,1200] = A[M,300] * W[1200,300]^T + bias --
// BM=128 BN=128 BK=12, 256 threads, 8x8 per thread. z selects fwd/bwd.
__global__ __launch_bounds__(256) void k_gemm(
    const float* __restrict__ Wf, const float* __restrict__ bf,
    const float* __restrict__ Wb, const float* __restrict__ bb_) {
    const int M = B_*S_, N = G4, K = E_;
    const float* W    = blockIdx.z ? Wb  : Wf;
    const float* bias = blockIdx.z ? bb_ : bf;
    float* C          = blockIdx.z ? g_xgb : g_xgf;
    const float* A = g_mem;

    __shared__ float As[12][128];
    __shared__ float Bs[12][128];
    int tid = threadIdx.x;
    int tx = tid & 15, ty = tid >> 4;
    int m0 = blockIdx.x * 128, n0 = blockIdx.y * 128;

    float acc[8][8];
#pragma unroll
    for (int i = 0; i < 8; i++)
#pragma unroll
        for (int j = 0; j < 8; j++) acc[i][j] = 0.f;

    for (int kt = 0; kt < 25; kt++) {
        int k0 = kt * 12;
        for (int idx = tid; idx < 384; idx += 256) {
            int m = idx / 3, x = idx % 3;
            float4 v = *(const float4*)(A + (size_t)(m0 + m) * K + k0 + 4 * x);
            As[4*x+0][m] = v.x; As[4*x+1][m] = v.y;
            As[4*x+2][m] = v.z; As[4*x+3][m] = v.w;
        }
        for (int idx = tid; idx < 384; idx += 256) {
            int n = idx / 3, x = idx % 3;
            float4 v = make_float4(0.f,0.f,0.f,0.f);
            if (n0 + n < N) v = *(const float4*)(W + (size_t)(n0 + n) * K + k0 + 4 * x);
            Bs[4*x+0][n] = v.x; Bs[4*x+1][n] = v.y;
            Bs[4*x+2][n] = v.z; Bs[4*x+3][n] = v.w;
        }
        __syncthreads();
#pragma unroll
        for (int k = 0; k < 12; k++) {
            float4 a1 = *(const float4*)&As[k][ty*8];
            float4 a2 = *(const float4*)&As[k][ty*8+4];
            float4 b1 = *(const float4*)&Bs[k][tx*8];
            float4 b2 = *(const float4*)&Bs[k][tx*8+4];
            float av[8] = {a1.x,a1.y,a1.z,a1.w,a2.x,a2.y,a2.z,a2.w};
            float bv[8] = {b1.x,b1.y,b1.z,b1.w,b2.x,b2.y,b2.z,b2.w};
#pragma unroll
            for (int i = 0; i < 8; i++)
#pragma unroll
                for (int j = 0; j < 8; j++) acc[i][j] += av[i]*bv[j];
        }
        __syncthreads();
    }
#pragma unroll
    for (int i = 0; i < 8; i++) {
        int m = m0 + ty*8 + i;
#pragma unroll
        for (int j = 0; j < 8; j++) {
            int n = n0 + tx*8 + j;
            if (n < N) C[(size_t)m * N + n] = acc[i][j] + bias[n];
        }
    }
}

// ---------------- K3: bidirectional LSTM scan -------------------------------
// grid 64: bx<32 forward, else backward. 4 batches/block. 320 threads.
__device__ __forceinline__ float sigm(float x) { return 1.f / (1.f + expf(-x)); }

__global__ __launch_bounds__(320) void k_scan(
    const float* __restrict__ Whf, const float* __restrict__ bhf,
    const float* __restrict__ Whb, const float* __restrict__ bhb) {
    __shared__ float h_s[4][300];
    __shared__ float g_s[4][1200];
    __shared__ float bhh_s[1200];
    __shared__ int len_s[4];
    __shared__ int maxlen_s;

    int dir = blockIdx.x >> 5;
    int b0  = (blockIdx.x & 31) * 4;
    const float* Whh = dir ? Whb : Whf;
    const float* bhh = dir ? bhb : bhf;
    const float* xg  = dir ? g_xgb : g_xgf;
    float* out       = dir ? g_outb : g_outf;
    int tid = threadIdx.x;

    if (tid < 4) len_s[tid] = g_mlen[b0 + tid];
    for (int i = tid; i < 1200; i += 320) bhh_s[i] = bhh[i];
    for (int i = tid; i < 300; i += 320) {
        h_s[0][i] = 0.f; h_s[1][i] = 0.f; h_s[2][i] = 0.f; h_s[3][i] = 0.f;
    }
    __syncthreads();
    if (tid == 0) {
        int m = len_s[0];
        for (int i = 1; i < 4; i++) m = max(m, len_s[i]);
        maxlen_s = m;
    }
    __syncthreads();
    const int L[4] = {len_s[0], len_s[1], len_s[2], len_s[3]};
    const int maxlen = maxlen_s;

    int j0 = tid, j1 = tid + 320, j2 = tid + 640, j3 = tid + 960;
    bool v3 = (j3 < 1200);
    const float4* w0 = (const float4*)(Whh + (size_t)j0 * 300);
    const float4* w1 = (const float4*)(Whh + (size_t)j1 * 300);
    const float4* w2 = (const float4*)(Whh + (size_t)j2 * 300);
    const float4* w3 = (const float4*)(Whh + (size_t)(v3 ? j3 : 0) * 300);
    float c0[4] = {0.f, 0.f, 0.f, 0.f};

    for (int t = 0; t < S_; t++) {
        if (t < maxlen) {
            float acc[4][4];
            const float* xr[4];
#pragma unroll
            for (int bb = 0; bb < 4; bb++) {
                int s = dir ? (L[bb] - 1 - t) : t;
                if (s < 0) s = 0;
                xr[bb] = xg + ((size_t)(b0 + bb) * S_ + s) * G4;
            }
#pragma unroll
            for (int bb = 0; bb < 4; bb++) {
                acc[0][bb] = xr[bb][j0] + bhh_s[j0];
                acc[1][bb] = xr[bb][j1] + bhh_s[j1];
                acc[2][bb] = xr[bb][j2] + bhh_s[j2];
                acc[3][bb] = v3 ? (xr[bb][j3] + bhh_s[j3]) : 0.f;
            }
            const float4* h40 = (const float4*)h_s[0];
            const float4* h41 = (const float4*)h_s[1];
            const float4* h42 = (const float4*)h_s[2];
            const float4* h43 = (const float4*)h_s[3];
#pragma unroll 3
            for (int k = 0; k < 75; k++) {
                float4 ha = h40[k], hb = h41[k], hc = h42[k], hd = h43[k];
                float4 wa = w0[k], wb = w1[k], wc = w2[k], wd = w3[k];
                acc[0][0] += wa.x*ha.x + wa.y*ha.y + wa.z*ha.z + wa.w*ha.w;
                acc[0][1] += wa.x*hb.x + wa.y*hb.y + wa.z*hb.z + wa.w*hb.w;
                acc[0][2] += wa.x*hc.x + wa.y*hc.y + wa.z*hc.z + wa.w*hc.w;
                acc[0][3] += wa.x*hd.x + wa.y*hd.y + wa.z*hd.z + wa.w*hd.w;
                acc[1][0] += wb.x*ha.x + wb.y*ha.y + wb.z*ha.z + wb.w*ha.w;
                acc[1][1] += wb.x*hb.x + wb.y*hb.y + wb.z*hb.z + wb.w*hb.w;
                acc[1][2] += wb.x*hc.x + wb.y*hc.y + wb.z*hc.z + wb.w*hc.w;
                acc[1][3] += wb.x*hd.x + wb.y*hd.y + wb.z*hd.z + wb.w*hd.w;
                acc[2][0] += wc.x*ha.x + wc.y*ha.y + wc.z*ha.z + wc.w*ha.w;
                acc[2][1] += wc.x*hb.x + wc.y*hb.y + wc.z*hb.z + wc.w*hb.w;
                acc[2][2] += wc.x*hc.x + wc.y*hc.y + wc.z*hc.z + wc.w*hc.w;
                acc[2][3] += wc.x*hd.x + wc.y*hd.y + wc.z*hd.z + wc.w*hd.w;
                acc[3][0] += wd.x*ha.x + wd.y*ha.y + wd.z*ha.z + wd.w*ha.w;
                acc[3][1] += wd.x*hb.x + wd.y*hb.y + wd.z*hb.z + wd.w*hb.w;
                acc[3][2] += wd.x*hc.x + wd.y*hc.y + wd.z*hc.z + wd.w*hc.w;
                acc[3][3] += wd.x*hd.x + wd.y*hd.y + wd.z*hd.z + wd.w*hd.w;
            }
#pragma unroll
            for (int bb = 0; bb < 4; bb++) {
                g_s[bb][j0] = acc[0][bb];
                g_s[bb][j1] = acc[1][bb];
                g_s[bb][j2] = acc[2][bb];
                if (v3) g_s[bb][j3] = acc[3][bb];
            }
            __syncthreads();
            if (tid < 300) {
                int m = tid;
#pragma unroll
                for (int bb = 0; bb < 4; bb++) {
                    if (t < L[bb]) {
                        float ig = sigm(g_s[bb][m]);
                        float fg = sigm(g_s[bb][m + 300]);
                        float gg = tanhf(g_s[bb][m + 600]);
                        float og = sigm(g_s[bb][m + 900]);
                        float c = fg * c0[bb] + ig * gg;
                        c0[bb] = c;
                        float hn = og * tanhf(c);
                        h_s[bb][m] = hn;
                        int s = dir ? (L[bb] - 1 - t) : t;
                        out[((size_t)(b0 + bb) * S_ + s) * H_ + m] = hn;
                    } else {
                        out[((size_t)(b0 + bb) * S_ + t) * H_ + m] = 0.f;
                    }
                }
            }
            __syncthreads();
        } else {
            if (tid < 300)
                for (int bb = 0; bb < 4; bb++)
                    out[((size_t)(b0 + bb) * S_ + t) * H_ + tid] = 0.f;
        }
    }
}

// ---------------- K4: location weights + attention + pooling ----------------
// alpha is hop-invariant (softmax shift invariance) -> compute i once.
__global__ __launch_bounds__(256) void k_attn(const float* __restrict__ attW) {
    __shared__ float attw_s[1204];
    __shared__ float aw_s[256];   // alpha * w
    __shared__ float au_s[256];   // alpha * u
    __shared__ float red[256];
    int b = blockIdx.x, t = threadIdx.x;
    for (int i = t; i < 1201; i += 256) attw_s[i] = attW[i];
    __syncthreads();

    float ml = (float)g_mlen[b], ll = (float)g_llen[b], al = (float)g_alen[b];
    float pos = (float)t;
    float w, u;
    if (pos < ll)                      { w = 1.f - (ll - pos) / ml;            u = pos - ll; }
    else if (pos >= ll + al && pos < ml){ w = 1.f - (pos - ll - al + 1.f) / ml; u = pos - ll - al + 1.f; }
    else                               { w = 1.f; u = 0.f; }

    const float4* rf = (const float4*)(g_outf + ((size_t)b * S_ + t) * H_);
    const float4* rb = (const float4*)(g_outb + ((size_t)b * S_ + t) * H_);
    float dot = 0.f;
#pragma unroll 5
    for (int k = 0; k < 75; k++) {
        float4 a = rf[k]; float4 wv = *(const float4*)&attw_s[4 * k];
        dot += a.x*wv.x + a.y*wv.y + a.z*wv.z + a.w*wv.w;
        float4 c = rb[k]; float4 wv2 = *(const float4*)&attw_s[300 + 4 * k];
        dot += c.x*wv2.x + c.y*wv2.y + c.z*wv2.z + c.w*wv2.w;
    }
    float score = w * dot + u * attw_s[600];

    red[t] = score; __syncthreads();
    for (int off = 128; off > 0; off >>= 1) {
        if (t < off) red[t] = fmaxf(red[t], red[t + off]);
        __syncthreads();
    }
    float mx = red[0]; __syncthreads();
    float e = expf(score - mx);
    red[t] = e; __syncthreads();
    for (int off = 128; off > 0; off >>= 1) {
        if (t < off) red[t] += red[t + off];
        __syncthreads();
    }
    float alpha = e / red[0];
    aw_s[t] = alpha * w;
    au_s[t] = alpha * u;
    __syncthreads();

    for (int d = t; d < DIV; d += 256) {
        float acc = 0.f;
        if (d < 300) {
            const float* p = g_outf + (size_t)b * S_ * H_ + d;
            for (int s = 0; s < S_; s++) acc += aw_s[s] * p[(size_t)s * H_];
        } else if (d < 600) {
            const float* p = g_outb + (size_t)b * S_ * H_ + (d - 300);
            for (int s = 0; s < S_; s++) acc += aw_s[s] * p[(size_t)s * H_];
        } else {
            for (int s = 0; s < S_; s++) acc += au_s[s];
        }
        g_ivec[b * DIV + d] = acc;
    }
}

// ---------------- K5: 3 GRU hops + dense ------------------------------------
__global__ __launch_bounds__(320) void k_final(
    const float* __restrict__ Wih, const float* __restrict__ Whh,
    const float* __restrict__ bih, const float* __restrict__ bhh,
    const float* __restrict__ dW,  const float* __restrict__ db,
    float* __restrict__ outp) {
    __shared__ float iv[601];
    __shared__ float et[300];
    __shared__ float red[320];
    int b = blockIdx.x, t = threadIdx.x;
    for (int i = t; i < DIV; i += 320) iv[i] = g_ivec[b * DIV + i];
    if (t < 300) et[t] = 0.f;
    __syncthreads();

    float gir = 0.f, giz = 0.f, gin = 0.f;
    if (t < 300) {
        const float* wr = Wih + (size_t)t * DIV;
        const float* wz = Wih + (size_t)(300 + t) * DIV;
        const float* wn = Wih + (size_t)(600 + t) * DIV;
        float s1 = 0.f, s2 = 0.f, s3 = 0.f;
        for (int k = 0; k < DIV; k++) {
            float x = iv[k];
            s1 += wr[k] * x; s2 += wz[k] * x; s3 += wn[k] * x;
        }
        gir = s1 + bih[t]; giz = s2 + bih[300 + t]; gin = s3 + bih[600 + t];
    }
    for (int hop = 0; hop < 3; hop++) {
        float newet = 0.f;
        if (t < 300) {
            const float* wr = Whh + (size_t)t * 300;
            const float* wz = Whh + (size_t)(300 + t) * 300;
            const float* wn = Whh + (size_t)(600 + t) * 300;
            float s1 = 0.f, s2 = 0.f, s3 = 0.f;
            for (int k = 0; k < 300; k++) {
                float h = et[k];
                s1 += wr[k] * h; s2 += wz[k] * h; s3 += wn[k] * h;
            }
            float ghr = s1 + bhh[t], ghz = s2 + bhh[300 + t], ghn = s3 + bhh[600 + t];
            float r = sigm(gir + ghr);
            float z = sigm(giz + ghz);
            float n = tanhf(gin + r * ghn);
            newet = (1.f - z) * n + z * et[t];
        }
        __syncthreads();
        if (t < 300) et[t] = newet;
        __syncthreads();
    }
    for (int c = 0; c < 3; c++) {
        red[t] = (t < 300) ? et[t] * dW[c * 300 + t] : 0.f;
        __syncthreads();
        if (t < 160) red[t] += red[t + 160]; __syncthreads();
        if (t < 80)  red[t] += red[t + 80];  __syncthreads();
        if (t < 40)  red[t] += red[t + 40];  __syncthreads();
        if (t < 20)  red[t] += red[t + 20];  __syncthreads();
        if (t < 10)  red[t] += red[t + 10];  __syncthreads();
        if (t < 5)   red[t] += red[t + 5];   __syncthreads();
        if (t == 0) {
            float s = red[0] + red[1] + red[2] + red[3] + red[4];
            outp[b * 3 + c] = s + db[c];
        }
        __syncthreads();
    }
}

// ---------------- launch -----------------------------------------------------
extern "C" void kernel_launch(void* const* d_in, const int* in_sizes, int n_in,
                              void* d_out, int out_size) {
    const int*   text      = (const int*)  d_in[0];
    const int*   aspect    = (const int*)  d_in[1];
    const int*   leftc     = (const int*)  d_in[2];
    const float* embedding = (const float*)d_in[3];
    const float* Wih_f     = (const float*)d_in[4];
    const float* Whh_f     = (const float*)d_in[5];
    const float* bih_f     = (const float*)d_in[6];
    const float* bhh_f     = (const float*)d_in[7];
    const float* Wih_b     = (const float*)d_in[8];
    const float* Whh_b     = (const float*)d_in[9];
    const float* bih_b     = (const float*)d_in[10];
    const float* bhh_b     = (const float*)d_in[11];
    const float* att_W     = (const float*)d_in[12];
    // d_in[13] att_b : drops out of softmax (shift invariance)
    const float* gru_Wih   = (const float*)d_in[14];
    const float* gru_Whh   = (const float*)d_in[15];
    const float* gru_bih   = (const float*)d_in[16];
    const float* gru_bhh   = (const float*)d_in[17];
    const float* dense_W   = (const float*)d_in[18];
    const float* dense_b   = (const float*)d_in[19];
    float* outp = (float*)d_out;

    k_prep<<<B_, 256>>>(text, aspect, leftc);
    k_embed<<<B_ * S_, 96>>>(text, embedding);
    k_gemm<<<dim3(B_ * S_ / 128, (G4 + 127) / 128, 2), 256>>>(Wih_f, bih_f, Wih_b, bih_b);
    k_scan<<<64, 320>>>(Whh_f, bhh_f, Whh_b, bhh_b);
    k_attn<<<B_, 256>>>(att_W);
    k_final<<<B_, 320>>>(gru_Wih, gru_Whh, gru_bih, gru_bhh, dense_W, dense_b, outp);
}

// round 3
// speedup vs baseline: 1.6224x; 1.6224x over previous
#include <cuda_runtime.h>
#include <math.h>
#include <stdint.h>

#define B_ 128
#define S_ 256
#define E_ 300
#define H_ 300
#define G4 1200   // 4*H
#define DIV 601   // 2H+1
#define NM 38     // h-slice per cluster CTA (8*38=304 >= 300)
#define HPAD 312  // padded h stride (bank-conflict-free across bb)

// ---------------- scratch (device globals; no allocations allowed) ----------
__device__ float g_mem [B_*S_*E_];
__device__ float g_xgf [B_*S_*G4];
__device__ float g_xgb [B_*S_*G4];
__device__ float g_outf[B_*S_*H_];
__device__ float g_outb[B_*S_*H_];
__device__ float g_ivec[B_*DIV];
__device__ int   g_mlen[B_], g_llen[B_], g_alen[B_];

__device__ __forceinline__ float sigm(float x) { return 1.f / (1.f + expf(-x)); }

__device__ __forceinline__ uint32_t smem_u32(const void* p) {
    uint32_t a;
    asm("{ .reg .u64 t; cvta.to.shared.u64 t, %1; cvt.u32.u64 %0, t; }" : "=r"(a) : "l"(p));
    return a;
}

// ---------------- K0: lengths ----------------------------------------------
__global__ void k_prep(const int* __restrict__ text,
                       const int* __restrict__ aspect,
                       const int* __restrict__ leftc) {
    int b = blockIdx.x, t = threadIdx.x;
    int c1 = __syncthreads_count(text[b*S_ + t] != 0);
    int c2 = __syncthreads_count(leftc[b*S_ + t] != 0);
    int c3 = __syncthreads_count(t < 8 && aspect[b*8 + t] != 0);
    if (t == 0) { g_mlen[b] = c1; g_llen[b] = c2; g_alen[b] = c3; }
}

// ---------------- K1: embedding gather --------------------------------------
__global__ void k_embed(const int* __restrict__ text,
                        const float* __restrict__ emb) {
    int r = blockIdx.x;
    int id = text[r];
    const float4* src = (const float4*)(emb + (size_t)id * E_);
    float4* dst = (float4*)(g_mem + (size_t)r * E_);
    int t = threadIdx.x;
    if (t < 75) dst[t] = src[t];
}

// ---------------- K2: xg GEMM ------------------------------------------------
__global__ __launch_bounds__(256) void k_gemm(
    const float* __restrict__ Wf, const float* __restrict__ bf,
    const float* __restrict__ Wb, const float* __restrict__ bb_) {
    const int M = B_*S_, N = G4, K = E_;
    const float* W    = blockIdx.z ? Wb  : Wf;
    const float* bias = blockIdx.z ? bb_ : bf;
    float* C          = blockIdx.z ? g_xgb : g_xgf;
    const float* A = g_mem;

    __shared__ float As[12][128];
    __shared__ float Bs[12][128];
    int tid = threadIdx.x;
    int tx = tid & 15, ty = tid >> 4;
    int m0 = blockIdx.x * 128, n0 = blockIdx.y * 128;

    float acc[8][8];
#pragma unroll
    for (int i = 0; i < 8; i++)
#pragma unroll
        for (int j = 0; j < 8; j++) acc[i][j] = 0.f;

    for (int kt = 0; kt < 25; kt++) {
        int k0 = kt * 12;
        for (int idx = tid; idx < 384; idx += 256) {
            int m = idx / 3, x = idx % 3;
            float4 v = *(const float4*)(A + (size_t)(m0 + m) * K + k0 + 4 * x);
            As[4*x+0][m] = v.x; As[4*x+1][m] = v.y;
            As[4*x+2][m] = v.z; As[4*x+3][m] = v.w;
        }
        for (int idx = tid; idx < 384; idx += 256) {
            int n = idx / 3, x = idx % 3;
            float4 v = make_float4(0.f,0.f,0.f,0.f);
            if (n0 + n < N) v = *(const float4*)(W + (size_t)(n0 + n) * K + k0 + 4 * x);
            Bs[4*x+0][n] = v.x; Bs[4*x+1][n] = v.y;
            Bs[4*x+2][n] = v.z; Bs[4*x+3][n] = v.w;
        }
        __syncthreads();
#pragma unroll
        for (int k = 0; k < 12; k++) {
            float4 a1 = *(const float4*)&As[k][ty*8];
            float4 a2 = *(const float4*)&As[k][ty*8+4];
            float4 b1 = *(const float4*)&Bs[k][tx*8];
            float4 b2 = *(const float4*)&Bs[k][tx*8+4];
            float av[8] = {a1.x,a1.y,a1.z,a1.w,a2.x,a2.y,a2.z,a2.w};
            float bv[8] = {b1.x,b1.y,b1.z,b1.w,b2.x,b2.y,b2.z,b2.w};
#pragma unroll
            for (int i = 0; i < 8; i++)
#pragma unroll
                for (int j = 0; j < 8; j++) acc[i][j] += av[i]*bv[j];
        }
        __syncthreads();
    }
#pragma unroll
    for (int i = 0; i < 8; i++) {
        int m = m0 + ty*8 + i;
#pragma unroll
        for (int j = 0; j < 8; j++) {
            int n = n0 + tx*8 + j;
            if (n < N) C[(size_t)m * N + n] = acc[i][j] + bias[n];
        }
    }
}

// ---------------- K3: clustered BiLSTM scan (weights SMEM-resident) ---------
// cluster = 8 CTAs, each owns 38 h-rows (x4 gates = 152 Whh rows in smem).
// blockIdx.x = cluster rank, blockIdx.y = group (32 fwd + 32 bwd, 4 batches each)
// dynamic smem layout (floats):
//   w_s   [152*300]       weight slice, row = m*4+gate
//   h_s   [2*4*HPAD]      double-buffered full h per batch
//   xg_s  [608]           staged xg,  index (bb*4+gate)*38+m
//   g_s   [608]           dot results, index bb + 4*gate + 16*m
//   bhh_s [152]           index gate*38+m
#define SCAN_SMEM_FLOATS (152*300 + 2*4*HPAD + 608 + 608 + 152)
#define SCAN_SMEM_BYTES  (SCAN_SMEM_FLOATS * 4)

__global__ void __cluster_dims__(8,1,1) __launch_bounds__(640, 1)
k_scan_cl(const float* __restrict__ Whf, const float* __restrict__ bhf,
          const float* __restrict__ Whb, const float* __restrict__ bhb) {
    extern __shared__ float sm[];
    float* w_s   = sm;
    float* h_s   = w_s + 152*300;
    float* xg_s  = h_s + 2*4*HPAD;
    float* g_s   = xg_s + 608;
    float* bhh_s = g_s + 608;
    __shared__ int len_s[4];
    __shared__ int maxlen_s;

    const int rank = blockIdx.x;
    const int grp  = blockIdx.y;
    const int dir  = grp >> 5;
    const int b0   = (grp & 31) * 4;
    const int m0   = rank * NM;
    const int nm   = min(NM, H_ - m0);     // 38, except 34 for rank 7
    const int tid  = threadIdx.x;

    const float* Whh = dir ? Whb : Whf;
    const float* bhh = dir ? bhb : bhf;
    const float* xg  = dir ? g_xgb : g_xgf;
    float* out       = dir ? g_outb : g_outf;

    // load weight slice (zero-pad rows beyond nm)
    for (int i = tid; i < 152*75; i += 640) {
        int row = i / 75, k4 = i % 75;
        int m = row >> 2, gate = row & 3;
        float4 v = make_float4(0.f,0.f,0.f,0.f);
        if (m < nm)
            v = *(const float4*)(Whh + (size_t)(gate*300 + m0 + m) * 300 + k4*4);
        *(float4*)(w_s + row*300 + k4*4) = v;
    }
    for (int i = tid; i < 152; i += 640) {
        int gate = i / 38, m = i % 38;
        bhh_s[i] = (m < nm) ? bhh[gate*300 + m0 + m] : 0.f;
    }
    for (int i = tid; i < 2*4*HPAD; i += 640) h_s[i] = 0.f;
    if (tid < 4) len_s[tid] = g_mlen[b0 + tid];
    __syncthreads();
    if (tid == 0) {
        int mx = len_s[0];
        for (int i = 1; i < 4; i++) mx = max(mx, len_s[i]);
        maxlen_s = mx;
    }
    __syncthreads();
    const int L0 = len_s[0], L1 = len_s[1], L2 = len_s[2], L3 = len_s[3];
    const int maxlen = maxlen_s;

    float c_reg = 0.f;                          // cell state for tid<152
    const int u_bb = tid & 3, u_m = tid >> 2;   // update role
    const int u_L  = (u_bb==0)?L0:(u_bb==1)?L1:(u_bb==2)?L2:L3;

    int buf = 0;
    for (int t = 0; t < maxlen; t++) {
        // stage xg for this step
        if (tid < 608) {
            int bb2 = tid / 152, rem = tid % 152, g2 = rem / 38, m2 = rem % 38;
            int Lb = (bb2==0)?L0:(bb2==1)?L1:(bb2==2)?L2:L3;
            int s = dir ? (Lb - 1 - t) : t; if (s < 0) s = 0;
            if (m2 < nm)
                xg_s[(bb2*4+g2)*38+m2] =
                    xg[((size_t)(b0+bb2)*S_ + s)*G4 + g2*300 + m0 + m2];
        }
        // dot product slice: thread (m,gate,bb)
        if (tid < 608) {
            int m = tid >> 4, gate = (tid >> 2) & 3, bb = tid & 3;
            const float4* w = (const float4*)(w_s + (m*4+gate)*300);
            const float4* h = (const float4*)(h_s + (buf*4 + bb)*HPAD);
            float a0=0.f, a1=0.f, a2=0.f, a3=0.f;
#pragma unroll 5
            for (int k = 0; k < 75; k++) {
                float4 wv = w[k], hv = h[k];
                a0 += wv.x*hv.x; a1 += wv.y*hv.y;
                a2 += wv.z*hv.z; a3 += wv.w*hv.w;
            }
            g_s[tid] = (a0+a1)+(a2+a3);
        }
        __syncthreads();
        // gate nonlinearity + h push to all cluster CTAs
        if (tid < 152) {
            int mg = m0 + u_m;
            if (mg < H_) {
                int base = u_bb + 16*u_m;
                float gi = g_s[base     ] + xg_s[(u_bb*4+0)*38+u_m] + bhh_s[0*38+u_m];
                float gf = g_s[base +  4] + xg_s[(u_bb*4+1)*38+u_m] + bhh_s[1*38+u_m];
                float gg = g_s[base +  8] + xg_s[(u_bb*4+2)*38+u_m] + bhh_s[2*38+u_m];
                float go = g_s[base + 12] + xg_s[(u_bb*4+3)*38+u_m] + bhh_s[3*38+u_m];
                float hw;
                if (t < u_L) {
                    float ig = sigm(gi), fg = sigm(gf);
                    float ggt = tanhf(gg), og = sigm(go);
                    float cn = fg * c_reg + ig * ggt;
                    c_reg = cn;
                    hw = og * tanhf(cn);
                    int s = dir ? (u_L - 1 - t) : t;
                    out[((size_t)(b0+u_bb)*S_ + s)*H_ + mg] = hw;
                } else {
                    hw = h_s[(buf*4 + u_bb)*HPAD + mg];   // carry old h
                    out[((size_t)(b0+u_bb)*S_ + t)*H_ + mg] = 0.f;
                }
                int nb = buf ^ 1;
                uint32_t laddr = smem_u32(&h_s[(nb*4 + u_bb)*HPAD + mg]);
#pragma unroll
                for (int r = 0; r < 8; r++) {
                    uint32_t raddr;
                    asm volatile("mapa.shared::cluster.u32 %0, %1, %2;"
                                 : "=r"(raddr) : "r"(laddr), "r"(r));
                    asm volatile("st.shared::cluster.f32 [%0], %1;"
                                 :: "r"(raddr), "f"(hw) : "memory");
                }
            }
        }
        asm volatile("barrier.cluster.arrive.aligned;" ::: "memory");
        asm volatile("barrier.cluster.wait.aligned;"   ::: "memory");
        buf ^= 1;
    }
    // tail: zero-fill padding timesteps (no syncs needed)
    for (int t = maxlen; t < S_; t++) {
        if (tid < 152) {
            int mg = m0 + u_m;
            if (mg < H_)
                out[((size_t)(b0+u_bb)*S_ + t)*H_ + mg] = 0.f;
        }
    }
}

// ---------------- K4: location weights + attention + pooling ----------------
__global__ __launch_bounds__(256) void k_attn(const float* __restrict__ attW) {
    __shared__ float attw_s[1204];
    __shared__ float aw_s[256];
    __shared__ float au_s[256];
    __shared__ float red[256];
    int b = blockIdx.x, t = threadIdx.x;
    for (int i = t; i < 1201; i += 256) attw_s[i] = attW[i];
    __syncthreads();

    float ml = (float)g_mlen[b], ll = (float)g_llen[b], al = (float)g_alen[b];
    float pos = (float)t;
    float w, u;
    if (pos < ll)                       { w = 1.f - (ll - pos) / ml;            u = pos - ll; }
    else if (pos >= ll + al && pos < ml){ w = 1.f - (pos - ll - al + 1.f) / ml; u = pos - ll - al + 1.f; }
    else                                { w = 1.f; u = 0.f; }

    const float4* rf = (const float4*)(g_outf + ((size_t)b * S_ + t) * H_);
    const float4* rb = (const float4*)(g_outb + ((size_t)b * S_ + t) * H_);
    float dot = 0.f;
#pragma unroll 5
    for (int k = 0; k < 75; k++) {
        float4 a = rf[k]; float4 wv = *(const float4*)&attw_s[4 * k];
        dot += a.x*wv.x + a.y*wv.y + a.z*wv.z + a.w*wv.w;
        float4 c = rb[k]; float4 wv2 = *(const float4*)&attw_s[300 + 4 * k];
        dot += c.x*wv2.x + c.y*wv2.y + c.z*wv2.z + c.w*wv2.w;
    }
    float score = w * dot + u * attw_s[600];

    red[t] = score; __syncthreads();
    for (int off = 128; off > 0; off >>= 1) {
        if (t < off) red[t] = fmaxf(red[t], red[t + off]);
        __syncthreads();
    }
    float mx = red[0]; __syncthreads();
    float e = expf(score - mx);
    red[t] = e; __syncthreads();
    for (int off = 128; off > 0; off >>= 1) {
        if (t < off) red[t] += red[t + off];
        __syncthreads();
    }
    float alpha = e / red[0];
    aw_s[t] = alpha * w;
    au_s[t] = alpha * u;
    __syncthreads();

    for (int d = t; d < DIV; d += 256) {
        float acc = 0.f;
        if (d < 300) {
            const float* p = g_outf + (size_t)b * S_ * H_ + d;
            for (int s = 0; s < S_; s++) acc += aw_s[s] * p[(size_t)s * H_];
        } else if (d < 600) {
            const float* p = g_outb + (size_t)b * S_ * H_ + (d - 300);
            for (int s = 0; s < S_; s++) acc += aw_s[s] * p[(size_t)s * H_];
        } else {
            for (int s = 0; s < S_; s++) acc += au_s[s];
        }
        g_ivec[b * DIV + d] = acc;
    }
}

// ---------------- K5: 3 GRU hops + dense ------------------------------------
__global__ __launch_bounds__(320) void k_final(
    const float* __restrict__ Wih, const float* __restrict__ Whh,
    const float* __restrict__ bih, const float* __restrict__ bhh,
    const float* __restrict__ dW,  const float* __restrict__ db,
    float* __restrict__ outp) {
    __shared__ float iv[601];
    __shared__ float et[300];
    __shared__ float red[320];
    int b = blockIdx.x, t = threadIdx.x;
    for (int i = t; i < DIV; i += 320) iv[i] = g_ivec[b * DIV + i];
    if (t < 300) et[t] = 0.f;
    __syncthreads();

    float gir = 0.f, giz = 0.f, gin = 0.f;
    if (t < 300) {
        const float* wr = Wih + (size_t)t * DIV;
        const float* wz = Wih + (size_t)(300 + t) * DIV;
        const float* wn = Wih + (size_t)(600 + t) * DIV;
        float s1 = 0.f, s2 = 0.f, s3 = 0.f;
        for (int k = 0; k < DIV; k++) {
            float x = iv[k];
            s1 += wr[k] * x; s2 += wz[k] * x; s3 += wn[k] * x;
        }
        gir = s1 + bih[t]; giz = s2 + bih[300 + t]; gin = s3 + bih[600 + t];
    }
    for (int hop = 0; hop < 3; hop++) {
        float newet = 0.f;
        if (t < 300) {
            const float* wr = Whh + (size_t)t * 300;
            const float* wz = Whh + (size_t)(300 + t) * 300;
            const float* wn = Whh + (size_t)(600 + t) * 300;
            float s1 = 0.f, s2 = 0.f, s3 = 0.f;
            for (int k = 0; k < 300; k++) {
                float h = et[k];
                s1 += wr[k] * h; s2 += wz[k] * h; s3 += wn[k] * h;
            }
            float ghr = s1 + bhh[t], ghz = s2 + bhh[300 + t], ghn = s3 + bhh[600 + t];
            float r = sigm(gir + ghr);
            float z = sigm(giz + ghz);
            float n = tanhf(gin + r * ghn);
            newet = (1.f - z) * n + z * et[t];
        }
        __syncthreads();
        if (t < 300) et[t] = newet;
        __syncthreads();
    }
    for (int c = 0; c < 3; c++) {
        red[t] = (t < 300) ? et[t] * dW[c * 300 + t] : 0.f;
        __syncthreads();
        if (t < 160) red[t] += red[t + 160]; __syncthreads();
        if (t < 80)  red[t] += red[t + 80];  __syncthreads();
        if (t < 40)  red[t] += red[t + 40];  __syncthreads();
        if (t < 20)  red[t] += red[t + 20];  __syncthreads();
        if (t < 10)  red[t] += red[t + 10];  __syncthreads();
        if (t < 5)   red[t] += red[t + 5];   __syncthreads();
        if (t == 0) {
            float s = red[0] + red[1] + red[2] + red[3] + red[4];
            outp[b * 3 + c] = s + db[c];
        }
        __syncthreads();
    }
}

// ---------------- launch -----------------------------------------------------
extern "C" void kernel_launch(void* const* d_in, const int* in_sizes, int n_in,
                              void* d_out, int out_size) {
    const int*   text      = (const int*)  d_in[0];
    const int*   aspect    = (const int*)  d_in[1];
    const int*   leftc     = (const int*)  d_in[2];
    const float* embedding = (const float*)d_in[3];
    const float* Wih_f     = (const float*)d_in[4];
    const float* Whh_f     = (const float*)d_in[5];
    const float* bih_f     = (const float*)d_in[6];
    const float* bhh_f     = (const float*)d_in[7];
    const float* Wih_b     = (const float*)d_in[8];
    const float* Whh_b     = (const float*)d_in[9];
    const float* bih_b     = (const float*)d_in[10];
    const float* bhh_b     = (const float*)d_in[11];
    const float* att_W     = (const float*)d_in[12];
    const float* gru_Wih   = (const float*)d_in[14];
    const float* gru_Whh   = (const float*)d_in[15];
    const float* gru_bih   = (const float*)d_in[16];
    const float* gru_bhh   = (const float*)d_in[17];
    const float* dense_W   = (const float*)d_in[18];
    const float* dense_b   = (const float*)d_in[19];
    float* outp = (float*)d_out;

    cudaFuncSetAttribute(k_scan_cl, cudaFuncAttributeMaxDynamicSharedMemorySize,
                         SCAN_SMEM_BYTES);

    k_prep<<<B_, 256>>>(text, aspect, leftc);
    k_embed<<<B_ * S_, 96>>>(text, embedding);
    k_gemm<<<dim3(B_ * S_ / 128, (G4 + 127) / 128, 2), 256>>>(Wih_f, bih_f, Wih_b, bih_b);
    k_scan_cl<<<dim3(8, 64), 640, SCAN_SMEM_BYTES>>>(Whh_f, bhh_f, Whh_b, bhh_b);
    k_attn<<<B_, 256>>>(att_W);
    k_final<<<B_, 320>>>(gru_Wih, gru_Whh, gru_bih, gru_bhh, dense_W, dense_b, outp);
}

// round 4
// speedup vs baseline: 2.2904x; 1.4118x over previous
#include <cuda_runtime.h>
#include <math.h>
#include <stdint.h>

#define B_ 128
#define S_ 256
#define E_ 300
#define H_ 300
#define G4 1200   // 4*H
#define DIV 601   // 2H+1
#define NM 38     // h-slice per cluster CTA (8*38=304 >= 300)
#define KC 5      // k-chunks per row
#define CHF 60    // floats per chunk (5*60=300)
#define HPAD2 304 // padded h stride (16B-aligned rows)

// ---------------- scratch ----------------------------------------------------
__device__ float g_mem [B_*S_*E_];
__device__ float g_xgf [B_*S_*G4];
__device__ float g_xgb [B_*S_*G4];
__device__ float g_outf[B_*S_*H_];
__device__ float g_outb[B_*S_*H_];
__device__ float g_ivec[B_*DIV];
__device__ int   g_mlen[B_], g_llen[B_], g_alen[B_];

__device__ __forceinline__ float sigm(float x) { return 1.f / (1.f + expf(-x)); }

__device__ __forceinline__ uint32_t smem_u32(const void* p) {
    uint32_t a;
    asm("{ .reg .u64 t; cvta.to.shared.u64 t, %1; cvt.u32.u64 %0, t; }" : "=r"(a) : "l"(p));
    return a;
}
__device__ __forceinline__ unsigned long long pack2(float a, float b) {
    unsigned long long r;
    asm("mov.b64 %0, {%1,%2};" : "=l"(r) : "f"(a), "f"(b));
    return r;
}
__device__ __forceinline__ void fma2(unsigned long long& acc,
                                     unsigned long long a, unsigned long long b) {
    asm("fma.rn.f32x2 %0, %1, %2, %0;" : "+l"(acc) : "l"(a), "l"(b));
}
__device__ __forceinline__ float2 unpack2(unsigned long long v) {
    float2 f;
    asm("mov.b64 {%0,%1}, %2;" : "=f"(f.x), "=f"(f.y) : "l"(v));
    return f;
}
__device__ __forceinline__ void lds2u64(unsigned long long& a, unsigned long long& b,
                                        uint32_t addr) {
    asm volatile("ld.shared.v2.b64 {%0,%1}, [%2];" : "=l"(a), "=l"(b) : "r"(addr));
}

// ---------------- K0: lengths ------------------------------------------------
__global__ void k_prep(const int* __restrict__ text,
                       const int* __restrict__ aspect,
                       const int* __restrict__ leftc) {
    int b = blockIdx.x, t = threadIdx.x;
    int c1 = __syncthreads_count(text[b*S_ + t] != 0);
    int c2 = __syncthreads_count(leftc[b*S_ + t] != 0);
    int c3 = __syncthreads_count(t < 8 && aspect[b*8 + t] != 0);
    if (t == 0) { g_mlen[b] = c1; g_llen[b] = c2; g_alen[b] = c3; }
}

// ---------------- K1: embedding gather --------------------------------------
__global__ void k_embed(const int* __restrict__ text,
                        const float* __restrict__ emb) {
    int r = blockIdx.x;
    int id = text[r];
    const float4* src = (const float4*)(emb + (size_t)id * E_);
    float4* dst = (float4*)(g_mem + (size_t)r * E_);
    int t = threadIdx.x;
    if (t < 75) dst[t] = src[t];
}

// ---------------- K2: xg GEMM (f32x2 packed) ---------------------------------
__global__ __launch_bounds__(256) void k_gemm(
    const float* __restrict__ Wf, const float* __restrict__ bf,
    const float* __restrict__ Wb, const float* __restrict__ bb_) {
    const int N = G4, K = E_;
    const float* W    = blockIdx.z ? Wb  : Wf;
    const float* bias = blockIdx.z ? bb_ : bf;
    float* C          = blockIdx.z ? g_xgb : g_xgf;
    const float* A = g_mem;

    __shared__ __align__(16) float As[12][128];
    __shared__ __align__(16) float Bs[12][128];
    int tid = threadIdx.x;
    int tx = tid & 15, ty = tid >> 4;
    int m0 = blockIdx.x * 128, n0 = blockIdx.y * 128;

    unsigned long long acc2[8][4];
#pragma unroll
    for (int i = 0; i < 8; i++)
#pragma unroll
        for (int j = 0; j < 4; j++) acc2[i][j] = 0ull;

    for (int kt = 0; kt < 25; kt++) {
        int k0 = kt * 12;
        for (int idx = tid; idx < 384; idx += 256) {
            int m = idx / 3, x = idx % 3;
            float4 v = *(const float4*)(A + (size_t)(m0 + m) * K + k0 + 4 * x);
            As[4*x+0][m] = v.x; As[4*x+1][m] = v.y;
            As[4*x+2][m] = v.z; As[4*x+3][m] = v.w;
        }
        for (int idx = tid; idx < 384; idx += 256) {
            int n = idx / 3, x = idx % 3;
            float4 v = make_float4(0.f,0.f,0.f,0.f);
            if (n0 + n < N) v = *(const float4*)(W + (size_t)(n0 + n) * K + k0 + 4 * x);
            Bs[4*x+0][n] = v.x; Bs[4*x+1][n] = v.y;
            Bs[4*x+2][n] = v.z; Bs[4*x+3][n] = v.w;
        }
        __syncthreads();
#pragma unroll
        for (int k = 0; k < 12; k++) {
            float4 a1 = *(const float4*)&As[k][ty*8];
            float4 a2 = *(const float4*)&As[k][ty*8+4];
            float4 b1 = *(const float4*)&Bs[k][tx*8];
            float4 b2 = *(const float4*)&Bs[k][tx*8+4];
            unsigned long long bp[4] = {
                pack2(b1.x,b1.y), pack2(b1.z,b1.w),
                pack2(b2.x,b2.y), pack2(b2.z,b2.w) };
            float av[8] = {a1.x,a1.y,a1.z,a1.w,a2.x,a2.y,a2.z,a2.w};
#pragma unroll
            for (int i = 0; i < 8; i++) {
                unsigned long long ad = pack2(av[i], av[i]);
                fma2(acc2[i][0], ad, bp[0]);
                fma2(acc2[i][1], ad, bp[1]);
                fma2(acc2[i][2], ad, bp[2]);
                fma2(acc2[i][3], ad, bp[3]);
            }
        }
        __syncthreads();
    }
#pragma unroll
    for (int i = 0; i < 8; i++) {
        int m = m0 + ty*8 + i;
#pragma unroll
        for (int jp = 0; jp < 4; jp++) {
            float2 v = unpack2(acc2[i][jp]);
            int n = n0 + tx*8 + 2*jp;
            if (n     < N) C[(size_t)m * N + n    ] = v.x + bias[n];
            if (n + 1 < N) C[(size_t)m * N + n + 1] = v.y + bias[n+1];
        }
    }
}

// ---------------- K3: clustered scan, weights in REGISTERS -------------------
// cluster = 8 CTAs; each CTA owns 38 h-rows (152 gate-rows).
// 768 threads: tid -> kc = tid/152 (0..4), row = tid%152 (row = m*4+gate).
// Each thread holds 30 f32x2 weight regs for (row, k in [kc*60, kc*60+60)).
__global__ void __cluster_dims__(8,1,1) __launch_bounds__(768, 1)
k_scan_reg(const float* __restrict__ Whf, const float* __restrict__ bhf,
           const float* __restrict__ Whb, const float* __restrict__ bhb) {
    __shared__ __align__(16) float h_s[2][4][HPAD2];
    __shared__ float xg_s[4][152];
    __shared__ float g_s[3200];          // row*21 + bb*5 + kc
    __shared__ float bhh_s[152];
    __shared__ int   len_s[4];
    __shared__ int   maxlen_s;

    const int rank = blockIdx.x;
    const int grp  = blockIdx.y;
    const int dir  = grp >> 5;
    const int b0   = (grp & 31) * 4;
    const int m0   = rank * NM;
    const int tid  = threadIdx.x;
    const bool act = tid < 760;
    const int kc   = act ? (tid / 152) : 0;
    const int row  = tid % 152;
    const int wm   = row >> 2, wg = row & 3;
    const bool wok = act && (m0 + wm < H_);

    const float* Whh = dir ? Whb : Whf;
    const float* bhh = dir ? bhb : bhf;
    const float* xg  = dir ? g_xgb : g_xgf;
    float* out       = dir ? g_outb : g_outf;

    if (tid < 4) len_s[tid] = g_mlen[b0 + tid];
    for (int i = tid; i < 2*4*HPAD2; i += 768) ((float*)h_s)[i] = 0.f;
    if (tid < 152) {
        int m2 = tid >> 2, g2 = tid & 3;
        bhh_s[tid] = (m0 + m2 < H_) ? bhh[g2*300 + m0 + m2] : 0.f;
    }

    // load weight slice into registers (one-time)
    unsigned long long w2[30];
    {
        const float* wr = Whh + (size_t)(wg*300 + m0 + wm) * 300 + kc*CHF;
#pragma unroll
        for (int j = 0; j < 30; j++) {
            float2 v = make_float2(0.f, 0.f);
            if (wok) v = *(const float2*)(wr + 2*j);
            w2[j] = pack2(v.x, v.y);
        }
    }
    __syncthreads();
    if (tid == 0) {
        int mx = len_s[0];
        for (int i = 1; i < 4; i++) mx = max(mx, len_s[i]);
        maxlen_s = mx;
    }
    __syncthreads();
    const int maxlen = maxlen_s;
    const int Lkc = len_s[kc < 4 ? kc : 0];

    // update-role constants (tid < 152)
    const int u_bb = tid & 3, u_m = tid >> 2;
    const int u_L  = len_s[u_bb];
    const int mg   = m0 + u_m;
    float c_reg = 0.f;

    const uint32_t h_base = smem_u32(&h_s[0][0][0]);
    int buf = 0;
    for (int t = 0; t < maxlen; t++) {
        // prefetch xg scalar (bb = kc), consumed after the dot loop
        float xgv = 0.f;
        if (tid < 608) {
            int s = dir ? (Lkc - 1 - t) : t;
            if (s < 0) s = 0;
            xgv = xg[((size_t)(b0 + kc)*S_ + s)*G4 + wg*300 + m0 + wm];
        }
        // dot: acc[bb] = sum_k w[k] * h[bb][kc*60+k]   (broadcast SMEM reads)
        if (act) {
            unsigned long long a0 = 0ull, a1 = 0ull, a2 = 0ull, a3 = 0ull;
            uint32_t hb = h_base + (uint32_t)(buf*4*HPAD2 + kc*CHF)*4u;
#pragma unroll
            for (int j = 0; j < 15; j++) {
                unsigned long long p, q;
                lds2u64(p, q, hb + j*16);
                fma2(a0, w2[2*j], p); fma2(a0, w2[2*j+1], q);
                lds2u64(p, q, hb + HPAD2*4 + j*16);
                fma2(a1, w2[2*j], p); fma2(a1, w2[2*j+1], q);
                lds2u64(p, q, hb + 2*HPAD2*4 + j*16);
                fma2(a2, w2[2*j], p); fma2(a2, w2[2*j+1], q);
                lds2u64(p, q, hb + 3*HPAD2*4 + j*16);
                fma2(a3, w2[2*j], p); fma2(a3, w2[2*j+1], q);
            }
            float2 f0 = unpack2(a0), f1 = unpack2(a1);
            float2 f2 = unpack2(a2), f3 = unpack2(a3);
            g_s[row*21 + 0*5 + kc] = f0.x + f0.y;
            g_s[row*21 + 1*5 + kc] = f1.x + f1.y;
            g_s[row*21 + 2*5 + kc] = f2.x + f2.y;
            g_s[row*21 + 3*5 + kc] = f3.x + f3.y;
            if (tid < 608) xg_s[kc][row] = xgv;
        }
        __syncthreads();
        // gate nonlinearity + h push to all cluster CTAs
        if (tid < 152 && mg < H_) {
            float gv[4];
#pragma unroll
            for (int g = 0; g < 4; g++) {
                int r2 = u_m*4 + g;
                float s_ = xg_s[u_bb][r2] + bhh_s[r2];
#pragma unroll
                for (int k2 = 0; k2 < KC; k2++) s_ += g_s[r2*21 + u_bb*5 + k2];
                gv[g] = s_;
            }
            float hw;
            if (t < u_L) {
                float ig = sigm(gv[0]), fg = sigm(gv[1]);
                float gt = tanhf(gv[2]), og = sigm(gv[3]);
                float cn = fg * c_reg + ig * gt;
                c_reg = cn;
                hw = og * tanhf(cn);
                int s = dir ? (u_L - 1 - t) : t;
                out[((size_t)(b0 + u_bb)*S_ + s)*H_ + mg] = hw;
            } else {
                hw = h_s[buf][u_bb][mg];
                out[((size_t)(b0 + u_bb)*S_ + t)*H_ + mg] = 0.f;
            }
            int nb = buf ^ 1;
            uint32_t laddr = smem_u32(&h_s[nb][u_bb][mg]);
#pragma unroll
            for (int r = 0; r < 8; r++) {
                uint32_t raddr;
                asm volatile("mapa.shared::cluster.u32 %0, %1, %2;"
                             : "=r"(raddr) : "r"(laddr), "r"(r));
                asm volatile("st.shared::cluster.f32 [%0], %1;"
                             :: "r"(raddr), "f"(hw) : "memory");
            }
        }
        asm volatile("barrier.cluster.arrive.aligned;" ::: "memory");
        asm volatile("barrier.cluster.wait.aligned;"   ::: "memory");
        buf ^= 1;
    }
    // tail zero-fill
    for (int t = maxlen; t < S_; t++)
        if (tid < 152 && mg < H_)
            out[((size_t)(b0 + u_bb)*S_ + t)*H_ + mg] = 0.f;
}

// ---------------- K4: attention ----------------------------------------------
__global__ __launch_bounds__(256) void k_attn(const float* __restrict__ attW) {
    __shared__ __align__(16) float attw_s[1204];
    __shared__ float aw_s[256];
    __shared__ float au_s[256];
    __shared__ float red[256];
    int b = blockIdx.x, t = threadIdx.x;
    for (int i = t; i < 1201; i += 256) attw_s[i] = attW[i];
    __syncthreads();

    float ml = (float)g_mlen[b], ll = (float)g_llen[b], al = (float)g_alen[b];
    float pos = (float)t;
    float w, u;
    if (pos < ll)                       { w = 1.f - (ll - pos) / ml;            u = pos - ll; }
    else if (pos >= ll + al && pos < ml){ w = 1.f - (pos - ll - al + 1.f) / ml; u = pos - ll - al + 1.f; }
    else                                { w = 1.f; u = 0.f; }

    const float4* rf = (const float4*)(g_outf + ((size_t)b * S_ + t) * H_);
    const float4* rb = (const float4*)(g_outb + ((size_t)b * S_ + t) * H_);
    float dot = 0.f;
#pragma unroll 5
    for (int k = 0; k < 75; k++) {
        float4 a = rf[k]; float4 wv = *(const float4*)&attw_s[4 * k];
        dot += a.x*wv.x + a.y*wv.y + a.z*wv.z + a.w*wv.w;
        float4 c = rb[k]; float4 wv2 = *(const float4*)&attw_s[300 + 4 * k];
        dot += c.x*wv2.x + c.y*wv2.y + c.z*wv2.z + c.w*wv2.w;
    }
    float score = w * dot + u * attw_s[600];

    red[t] = score; __syncthreads();
    for (int off = 128; off > 0; off >>= 1) {
        if (t < off) red[t] = fmaxf(red[t], red[t + off]);
        __syncthreads();
    }
    float mx = red[0]; __syncthreads();
    float e = expf(score - mx);
    red[t] = e; __syncthreads();
    for (int off = 128; off > 0; off >>= 1) {
        if (t < off) red[t] += red[t + off];
        __syncthreads();
    }
    float alpha = e / red[0];
    aw_s[t] = alpha * w;
    au_s[t] = alpha * u;
    __syncthreads();

    for (int d = t; d < DIV; d += 256) {
        float acc = 0.f;
        if (d < 300) {
            const float* p = g_outf + (size_t)b * S_ * H_ + d;
            for (int s = 0; s < S_; s++) acc += aw_s[s] * p[(size_t)s * H_];
        } else if (d < 600) {
            const float* p = g_outb + (size_t)b * S_ * H_ + (d - 300);
            for (int s = 0; s < S_; s++) acc += aw_s[s] * p[(size_t)s * H_];
        } else {
            for (int s = 0; s < S_; s++) acc += au_s[s];
        }
        g_ivec[b * DIV + d] = acc;
    }
}

// ---------------- K5: 3 GRU hops + dense -------------------------------------
__global__ __launch_bounds__(320) void k_final(
    const float* __restrict__ Wih, const float* __restrict__ Whh,
    const float* __restrict__ bih, const float* __restrict__ bhh,
    const float* __restrict__ dW,  const float* __restrict__ db,
    float* __restrict__ outp) {
    __shared__ float iv[601];
    __shared__ float et[300];
    __shared__ float red[320];
    int b = blockIdx.x, t = threadIdx.x;
    for (int i = t; i < DIV; i += 320) iv[i] = g_ivec[b * DIV + i];
    if (t < 300) et[t] = 0.f;
    __syncthreads();

    float gir = 0.f, giz = 0.f, gin = 0.f;
    if (t < 300) {
        const float* wr = Wih + (size_t)t * DIV;
        const float* wz = Wih + (size_t)(300 + t) * DIV;
        const float* wn = Wih + (size_t)(600 + t) * DIV;
        float s1 = 0.f, s2 = 0.f, s3 = 0.f;
        for (int k = 0; k < DIV; k++) {
            float x = iv[k];
            s1 += wr[k] * x; s2 += wz[k] * x; s3 += wn[k] * x;
        }
        gir = s1 + bih[t]; giz = s2 + bih[300 + t]; gin = s3 + bih[600 + t];
    }
    for (int hop = 0; hop < 3; hop++) {
        float newet = 0.f;
        if (t < 300) {
            const float* wr = Whh + (size_t)t * 300;
            const float* wz = Whh + (size_t)(300 + t) * 300;
            const float* wn = Whh + (size_t)(600 + t) * 300;
            float s1 = 0.f, s2 = 0.f, s3 = 0.f;
            for (int k = 0; k < 300; k++) {
                float h = et[k];
                s1 += wr[k] * h; s2 += wz[k] * h; s3 += wn[k] * h;
            }
            float ghr = s1 + bhh[t], ghz = s2 + bhh[300 + t], ghn = s3 + bhh[600 + t];
            float r = sigm(gir + ghr);
            float z = sigm(giz + ghz);
            float n = tanhf(gin + r * ghn);
            newet = (1.f - z) * n + z * et[t];
        }
        __syncthreads();
        if (t < 300) et[t] = newet;
        __syncthreads();
    }
    for (int c = 0; c < 3; c++) {
        red[t] = (t < 300) ? et[t] * dW[c * 300 + t] : 0.f;
        __syncthreads();
        if (t < 160) red[t] += red[t + 160]; __syncthreads();
        if (t < 80)  red[t] += red[t + 80];  __syncthreads();
        if (t < 40)  red[t] += red[t + 40];  __syncthreads();
        if (t < 20)  red[t] += red[t + 20];  __syncthreads();
        if (t < 10)  red[t] += red[t + 10];  __syncthreads();
        if (t < 5)   red[t] += red[t + 5];   __syncthreads();
        if (t == 0) {
            float s = red[0] + red[1] + red[2] + red[3] + red[4];
            outp[b * 3 + c] = s + db[c];
        }
        __syncthreads();
    }
}

// ---------------- launch -----------------------------------------------------
extern "C" void kernel_launch(void* const* d_in, const int* in_sizes, int n_in,
                              void* d_out, int out_size) {
    const int*   text      = (const int*)  d_in[0];
    const int*   aspect    = (const int*)  d_in[1];
    const int*   leftc     = (const int*)  d_in[2];
    const float* embedding = (const float*)d_in[3];
    const float* Wih_f     = (const float*)d_in[4];
    const float* Whh_f     = (const float*)d_in[5];
    const float* bih_f     = (const float*)d_in[6];
    const float* bhh_f     = (const float*)d_in[7];
    const float* Wih_b     = (const float*)d_in[8];
    const float* Whh_b     = (const float*)d_in[9];
    const float* bih_b     = (const float*)d_in[10];
    const float* bhh_b     = (const float*)d_in[11];
    const float* att_W     = (const float*)d_in[12];
    const float* gru_Wih   = (const float*)d_in[14];
    const float* gru_Whh   = (const float*)d_in[15];
    const float* gru_bih   = (const float*)d_in[16];
    const float* gru_bhh   = (const float*)d_in[17];
    const float* dense_W   = (const float*)d_in[18];
    const float* dense_b   = (const float*)d_in[19];
    float* outp = (float*)d_out;

    k_prep<<<B_, 256>>>(text, aspect, leftc);
    k_embed<<<B_ * S_, 96>>>(text, embedding);
    k_gemm<<<dim3(B_ * S_ / 128, (G4 + 127) / 128, 2), 256>>>(Wih_f, bih_f, Wih_b, bih_b);
    k_scan_reg<<<dim3(8, 64), 768>>>(Whh_f, bhh_f, Whh_b, bhh_b);
    k_attn<<<B_, 256>>>(att_W);
    k_final<<<B_, 320>>>(gru_Wih, gru_Whh, gru_bih, gru_bhh, dense_W, dense_b, outp);
}

// round 5
// speedup vs baseline: 2.7307x; 1.1922x over previous
#include <cuda_runtime.h>
#include <math.h>
#include <stdint.h>

#define B_ 128
#define S_ 256
#define E_ 300
#define H_ 300
#define G4 1200   // 4*H
#define DIV 601   // 2H+1
#define NM 38     // h-slice per cluster CTA (8*38=304 >= 300)
#define KC 5      // k-chunks per row
#define CHF 60    // floats per chunk
#define HPAD2 304 // padded h stride
#define NB 8      // batches per cluster

// ---------------- scratch ----------------------------------------------------
__device__ float g_mem [B_*S_*E_];
__device__ float g_xgf [B_*S_*G4];
__device__ float g_xgb [B_*S_*G4];
__device__ float g_outf[B_*S_*H_];
__device__ float g_outb[B_*S_*H_];
__device__ float g_ivec[B_*DIV];
__device__ int   g_mlen[B_], g_llen[B_], g_alen[B_];
__device__ int   g_perm[B_];

__device__ __forceinline__ float sigm(float x) { return 1.f / (1.f + expf(-x)); }

__device__ __forceinline__ uint32_t smem_u32(const void* p) {
    uint32_t a;
    asm("{ .reg .u64 t; cvta.to.shared.u64 t, %1; cvt.u32.u64 %0, t; }" : "=r"(a) : "l"(p));
    return a;
}
__device__ __forceinline__ unsigned long long pack2(float a, float b) {
    unsigned long long r;
    asm("mov.b64 %0, {%1,%2};" : "=l"(r) : "f"(a), "f"(b));
    return r;
}
__device__ __forceinline__ void fma2(unsigned long long& acc,
                                     unsigned long long a, unsigned long long b) {
    asm("fma.rn.f32x2 %0, %1, %2, %0;" : "+l"(acc) : "l"(a), "l"(b));
}
__device__ __forceinline__ float2 unpack2(unsigned long long v) {
    float2 f;
    asm("mov.b64 {%0,%1}, %2;" : "=f"(f.x), "=f"(f.y) : "l"(v));
    return f;
}
__device__ __forceinline__ void lds2u64(unsigned long long& a, unsigned long long& b,
                                        uint32_t addr) {
    asm volatile("ld.shared.v2.b64 {%0,%1}, [%2];" : "=l"(a), "=l"(b) : "r"(addr));
}

// ---------------- K0: lengths ------------------------------------------------
__global__ void k_prep(const int* __restrict__ text,
                       const int* __restrict__ aspect,
                       const int* __restrict__ leftc) {
    int b = blockIdx.x, t = threadIdx.x;
    int c1 = __syncthreads_count(text[b*S_ + t] != 0);
    int c2 = __syncthreads_count(leftc[b*S_ + t] != 0);
    int c3 = __syncthreads_count(t < 8 && aspect[b*8 + t] != 0);
    if (t == 0) { g_mlen[b] = c1; g_llen[b] = c2; g_alen[b] = c3; }
}

// ---------------- K0b: sort batches by length (bitonic, 1 block) -------------
__global__ void k_sort() {
    __shared__ int v[B_];
    int t = threadIdx.x;
    v[t] = (g_mlen[t] << 8) | t;
    __syncthreads();
    for (int k = 2; k <= B_; k <<= 1) {
        for (int j = k >> 1; j > 0; j >>= 1) {
            int ixj = t ^ j;
            if (ixj > t) {
                int a = v[t], b = v[ixj];
                bool up = ((t & k) == 0);
                if ((a > b) == up) { v[t] = b; v[ixj] = a; }
            }
            __syncthreads();
        }
    }
    g_perm[t] = v[t] & 255;
}

// ---------------- K1: embedding gather --------------------------------------
__global__ void k_embed(const int* __restrict__ text,
                        const float* __restrict__ emb) {
    int r = blockIdx.x;
    int id = text[r];
    const float4* src = (const float4*)(emb + (size_t)id * E_);
    float4* dst = (float4*)(g_mem + (size_t)r * E_);
    int t = threadIdx.x;
    if (t < 75) dst[t] = src[t];
}

// ---------------- K2: xg GEMM (f32x2 packed) ---------------------------------
__global__ __launch_bounds__(256) void k_gemm(
    const float* __restrict__ Wf, const float* __restrict__ bf,
    const float* __restrict__ Wb, const float* __restrict__ bb_) {
    const int N = G4, K = E_;
    const float* W    = blockIdx.z ? Wb  : Wf;
    const float* bias = blockIdx.z ? bb_ : bf;
    float* C          = blockIdx.z ? g_xgb : g_xgf;
    const float* A = g_mem;

    __shared__ __align__(16) float As[12][128];
    __shared__ __align__(16) float Bs[12][128];
    int tid = threadIdx.x;
    int tx = tid & 15, ty = tid >> 4;
    int m0 = blockIdx.x * 128, n0 = blockIdx.y * 128;

    unsigned long long acc2[8][4];
#pragma unroll
    for (int i = 0; i < 8; i++)
#pragma unroll
        for (int j = 0; j < 4; j++) acc2[i][j] = 0ull;

    for (int kt = 0; kt < 25; kt++) {
        int k0 = kt * 12;
        for (int idx = tid; idx < 384; idx += 256) {
            int m = idx / 3, x = idx % 3;
            float4 v = *(const float4*)(A + (size_t)(m0 + m) * K + k0 + 4 * x);
            As[4*x+0][m] = v.x; As[4*x+1][m] = v.y;
            As[4*x+2][m] = v.z; As[4*x+3][m] = v.w;
        }
        for (int idx = tid; idx < 384; idx += 256) {
            int n = idx / 3, x = idx % 3;
            float4 v = make_float4(0.f,0.f,0.f,0.f);
            if (n0 + n < N) v = *(const float4*)(W + (size_t)(n0 + n) * K + k0 + 4 * x);
            Bs[4*x+0][n] = v.x; Bs[4*x+1][n] = v.y;
            Bs[4*x+2][n] = v.z; Bs[4*x+3][n] = v.w;
        }
        __syncthreads();
#pragma unroll
        for (int k = 0; k < 12; k++) {
            float4 a1 = *(const float4*)&As[k][ty*8];
            float4 a2 = *(const float4*)&As[k][ty*8+4];
            float4 b1 = *(const float4*)&Bs[k][tx*8];
            float4 b2 = *(const float4*)&Bs[k][tx*8+4];
            unsigned long long bp[4] = {
                pack2(b1.x,b1.y), pack2(b1.z,b1.w),
                pack2(b2.x,b2.y), pack2(b2.z,b2.w) };
            float av[8] = {a1.x,a1.y,a1.z,a1.w,a2.x,a2.y,a2.z,a2.w};
#pragma unroll
            for (int i = 0; i < 8; i++) {
                unsigned long long ad = pack2(av[i], av[i]);
                fma2(acc2[i][0], ad, bp[0]);
                fma2(acc2[i][1], ad, bp[1]);
                fma2(acc2[i][2], ad, bp[2]);
                fma2(acc2[i][3], ad, bp[3]);
            }
        }
        __syncthreads();
    }
#pragma unroll
    for (int i = 0; i < 8; i++) {
        int m = m0 + ty*8 + i;
#pragma unroll
        for (int jp = 0; jp < 4; jp++) {
            float2 v = unpack2(acc2[i][jp]);
            int n = n0 + tx*8 + 2*jp;
            if (n     < N) C[(size_t)m * N + n    ] = v.x + bias[n];
            if (n + 1 < N) C[(size_t)m * N + n + 1] = v.y + bias[n+1];
        }
    }
}

// ---------------- K3: clustered scan, 8 batches, weights in registers --------
// cluster = 8 CTAs; each owns 38 h-rows (152 gate-rows). 768 threads.
// tid -> kc = tid/152 (0..4), row = tid%152 (row = m*4+gate).
// Dot runs 2 passes of 4 batches reusing the same 4 accumulator chains.
// dyn smem: h_s[2][8][HPAD2] | xg_s[8][152] | g_s[152*41] | bhh_s[152]
#define SC8_FLOATS (2*NB*HPAD2 + NB*152 + 152*41 + 152)
#define SC8_BYTES  (SC8_FLOATS*4)

__global__ void __cluster_dims__(8,1,1) __launch_bounds__(768, 1)
k_scan8(const float* __restrict__ Whf, const float* __restrict__ bhf,
        const float* __restrict__ Whb, const float* __restrict__ bhb) {
    extern __shared__ float sm[];
    float* h_s   = sm;                        // [2][8][HPAD2]
    float* xg_s  = h_s + 2*NB*HPAD2;          // [8][152]
    float* g_s   = xg_s + NB*152;             // row*41 + bb*5 + kc
    float* bhh_s = g_s + 152*41;
    __shared__ int len_s[NB], bset[NB];
    __shared__ int maxlen_s;

    const int rank = blockIdx.x;
    const int grp  = blockIdx.y;              // 0..31: 16 fwd, 16 bwd
    const int dir  = grp >> 4;
    const int gi   = grp & 15;
    const int m0   = rank * NM;
    const int tid  = threadIdx.x;
    const bool act = tid < 760;
    const int kc   = act ? (tid / 152) : 0;
    const int row  = tid % 152;
    const int wm   = row >> 2, wg = row & 3;
    const bool wok = act && (m0 + wm < H_);

    const float* Whh = dir ? Whb : Whf;
    const float* bhh = dir ? bhb : bhf;
    const float* xg  = dir ? g_xgb : g_xgf;
    float* out       = dir ? g_outb : g_outf;

    if (tid < NB) {
        int b = g_perm[gi*NB + tid];
        bset[tid]  = b;
        len_s[tid] = g_mlen[b];
    }
    for (int i = tid; i < 2*NB*HPAD2; i += 768) h_s[i] = 0.f;
    if (tid < 152) {
        int m2 = tid >> 2, g2 = tid & 3;
        bhh_s[tid] = (m0 + m2 < H_) ? bhh[g2*300 + m0 + m2] : 0.f;
    }

    // weights into registers (one-time)
    unsigned long long w2[30];
    {
        const float* wr = Whh + (size_t)(wg*300 + m0 + wm) * 300 + kc*CHF;
#pragma unroll
        for (int j = 0; j < 30; j++) {
            float2 v = make_float2(0.f, 0.f);
            if (wok) v = *(const float2*)(wr + 2*j);
            w2[j] = pack2(v.x, v.y);
        }
    }
    __syncthreads();
    if (tid == 0) {
        int mx = len_s[0];
        for (int i = 1; i < NB; i++) mx = max(mx, len_s[i]);
        maxlen_s = mx;
    }
    __syncthreads();
    const int maxlen = maxlen_s;

    // cluster-wide init fence: no CTA may receive pushes before its buffers exist
    asm volatile("barrier.cluster.arrive.aligned;" ::: "memory");
    asm volatile("barrier.cluster.wait.aligned;"   ::: "memory");

    // xg prefetch role (tid<608): bb0 = tid/152, bb1 = bb0+4, same row
    const int p_bb0 = tid / 152;               // valid when tid<608
    const int xcol  = wg*300 + m0 + wm;        // gate column (may exceed for pad rows)
    const bool xok  = (tid < 608) && (m0 + wm < H_);

    // update role (tid<304): u_bb = tid&7, u_m = tid>>3
    const int u_bb = tid & 7, u_m = tid >> 3;
    const bool uok = (tid < 304) && (m0 + u_m < H_);
    const int u_L  = len_s[u_bb & (NB-1)];
    const int u_b  = bset[u_bb & (NB-1)];
    const int mg   = m0 + u_m;
    float c_reg = 0.f;

    const uint32_t h_base = smem_u32(h_s);
    int buf = 0;
    for (int t = 0; t < maxlen; t++) {
        // prefetch xg for 8 batches (2 per thread)
        float xv0 = 0.f, xv1 = 0.f;
        if (xok) {
            int L0 = len_s[p_bb0], L1 = len_s[p_bb0 + 4];
            int s0 = dir ? (L0 - 1 - t) : t; if (s0 < 0) s0 = 0;
            int s1 = dir ? (L1 - 1 - t) : t; if (s1 < 0) s1 = 0;
            xv0 = xg[((size_t)bset[p_bb0    ]*S_ + s0)*G4 + xcol];
            xv1 = xg[((size_t)bset[p_bb0 + 4]*S_ + s1)*G4 + xcol];
        }
        // dot: 2 passes of 4 batches, reusing accumulator chains + weights
        if (act) {
#pragma unroll
            for (int p = 0; p < 2; p++) {
                unsigned long long a0 = 0ull, a1 = 0ull, a2 = 0ull, a3 = 0ull;
                uint32_t hb = h_base + (uint32_t)((buf*NB + 4*p)*HPAD2 + kc*CHF)*4u;
#pragma unroll
                for (int j = 0; j < 15; j++) {
                    unsigned long long q0, q1;
                    lds2u64(q0, q1, hb + j*16);
                    fma2(a0, w2[2*j], q0); fma2(a0, w2[2*j+1], q1);
                    lds2u64(q0, q1, hb + HPAD2*4 + j*16);
                    fma2(a1, w2[2*j], q0); fma2(a1, w2[2*j+1], q1);
                    lds2u64(q0, q1, hb + 2*HPAD2*4 + j*16);
                    fma2(a2, w2[2*j], q0); fma2(a2, w2[2*j+1], q1);
                    lds2u64(q0, q1, hb + 3*HPAD2*4 + j*16);
                    fma2(a3, w2[2*j], q0); fma2(a3, w2[2*j+1], q1);
                }
                float2 f0 = unpack2(a0), f1 = unpack2(a1);
                float2 f2 = unpack2(a2), f3 = unpack2(a3);
                g_s[row*41 + (4*p+0)*5 + kc] = f0.x + f0.y;
                g_s[row*41 + (4*p+1)*5 + kc] = f1.x + f1.y;
                g_s[row*41 + (4*p+2)*5 + kc] = f2.x + f2.y;
                g_s[row*41 + (4*p+3)*5 + kc] = f3.x + f3.y;
            }
        }
        if (tid < 608) {
            xg_s[p_bb0*152 + row]       = xv0;
            xg_s[(p_bb0 + 4)*152 + row] = xv1;
        }
        __syncthreads();
        // gate nonlinearity + push h to all 8 cluster CTAs
        if (uok) {
            float gv[4];
#pragma unroll
            for (int g = 0; g < 4; g++) {
                int r2 = u_m*4 + g;
                float s_ = xg_s[u_bb*152 + r2] + bhh_s[r2];
#pragma unroll
                for (int k2 = 0; k2 < KC; k2++) s_ += g_s[r2*41 + u_bb*5 + k2];
                gv[g] = s_;
            }
            float hw;
            if (t < u_L) {
                float ig = sigm(gv[0]), fg = sigm(gv[1]);
                float gt = tanhf(gv[2]), og = sigm(gv[3]);
                float cn = fg * c_reg + ig * gt;
                c_reg = cn;
                hw = og * tanhf(cn);
                int s = dir ? (u_L - 1 - t) : t;
                out[((size_t)u_b*S_ + s)*H_ + mg] = hw;
            } else {
                hw = h_s[(buf*NB + u_bb)*HPAD2 + mg];
                out[((size_t)u_b*S_ + t)*H_ + mg] = 0.f;
            }
            int nb2 = buf ^ 1;
            uint32_t laddr = smem_u32(&h_s[(nb2*NB + u_bb)*HPAD2 + mg]);
#pragma unroll
            for (int r = 0; r < 8; r++) {
                uint32_t raddr;
                asm volatile("mapa.shared::cluster.u32 %0, %1, %2;"
                             : "=r"(raddr) : "r"(laddr), "r"(r));
                asm volatile("st.shared::cluster.f32 [%0], %1;"
                             :: "r"(raddr), "f"(hw) : "memory");
            }
        }
        asm volatile("barrier.cluster.arrive.aligned;" ::: "memory");
        asm volatile("barrier.cluster.wait.aligned;"   ::: "memory");
        buf ^= 1;
    }
    // tail zero-fill
    for (int t = maxlen; t < S_; t++)
        if (uok)
            out[((size_t)u_b*S_ + t)*H_ + mg] = 0.f;
}

// ---------------- K4: attention ----------------------------------------------
__global__ __launch_bounds__(256) void k_attn(const float* __restrict__ attW) {
    __shared__ __align__(16) float attw_s[1204];
    __shared__ float aw_s[256];
    __shared__ float au_s[256];
    __shared__ float red[256];
    int b = blockIdx.x, t = threadIdx.x;
    for (int i = t; i < 1201; i += 256) attw_s[i] = attW[i];
    __syncthreads();

    float ml = (float)g_mlen[b], ll = (float)g_llen[b], al = (float)g_alen[b];
    float pos = (float)t;
    float w, u;
    if (pos < ll)                       { w = 1.f - (ll - pos) / ml;            u = pos - ll; }
    else if (pos >= ll + al && pos < ml){ w = 1.f - (pos - ll - al + 1.f) / ml; u = pos - ll - al + 1.f; }
    else                                { w = 1.f; u = 0.f; }

    const float4* rf = (const float4*)(g_outf + ((size_t)b * S_ + t) * H_);
    const float4* rb = (const float4*)(g_outb + ((size_t)b * S_ + t) * H_);
    float dot = 0.f;
#pragma unroll 5
    for (int k = 0; k < 75; k++) {
        float4 a = rf[k]; float4 wv = *(const float4*)&attw_s[4 * k];
        dot += a.x*wv.x + a.y*wv.y + a.z*wv.z + a.w*wv.w;
        float4 c = rb[k]; float4 wv2 = *(const float4*)&attw_s[300 + 4 * k];
        dot += c.x*wv2.x + c.y*wv2.y + c.z*wv2.z + c.w*wv2.w;
    }
    float score = w * dot + u * attw_s[600];

    red[t] = score; __syncthreads();
    for (int off = 128; off > 0; off >>= 1) {
        if (t < off) red[t] = fmaxf(red[t], red[t + off]);
        __syncthreads();
    }
    float mx = red[0]; __syncthreads();
    float e = expf(score - mx);
    red[t] = e; __syncthreads();
    for (int off = 128; off > 0; off >>= 1) {
        if (t < off) red[t] += red[t + off];
        __syncthreads();
    }
    float alpha = e / red[0];
    aw_s[t] = alpha * w;
    au_s[t] = alpha * u;
    __syncthreads();

    for (int d = t; d < DIV; d += 256) {
        float acc = 0.f;
        if (d < 300) {
            const float* p = g_outf + (size_t)b * S_ * H_ + d;
            for (int s = 0; s < S_; s++) acc += aw_s[s] * p[(size_t)s * H_];
        } else if (d < 600) {
            const float* p = g_outb + (size_t)b * S_ * H_ + (d - 300);
            for (int s = 0; s < S_; s++) acc += aw_s[s] * p[(size_t)s * H_];
        } else {
            for (int s = 0; s < S_; s++) acc += au_s[s];
        }
        g_ivec[b * DIV + d] = acc;
    }
}

// ---------------- K5: 3 GRU hops + dense -------------------------------------
__global__ __launch_bounds__(320) void k_final(
    const float* __restrict__ Wih, const float* __restrict__ Whh,
    const float* __restrict__ bih, const float* __restrict__ bhh,
    const float* __restrict__ dW,  const float* __restrict__ db,
    float* __restrict__ outp) {
    __shared__ float iv[601];
    __shared__ float et[300];
    __shared__ float red[320];
    int b = blockIdx.x, t = threadIdx.x;
    for (int i = t; i < DIV; i += 320) iv[i] = g_ivec[b * DIV + i];
    if (t < 300) et[t] = 0.f;
    __syncthreads();

    float gir = 0.f, giz = 0.f, gin = 0.f;
    if (t < 300) {
        const float* wr = Wih + (size_t)t * DIV;
        const float* wz = Wih + (size_t)(300 + t) * DIV;
        const float* wn = Wih + (size_t)(600 + t) * DIV;
        float s1 = 0.f, s2 = 0.f, s3 = 0.f;
        for (int k = 0; k < DIV; k++) {
            float x = iv[k];
            s1 += wr[k] * x; s2 += wz[k] * x; s3 += wn[k] * x;
        }
        gir = s1 + bih[t]; giz = s2 + bih[300 + t]; gin = s3 + bih[600 + t];
    }
    for (int hop = 0; hop < 3; hop++) {
        float newet = 0.f;
        if (t < 300) {
            const float* wr = Whh + (size_t)t * 300;
            const float* wz = Whh + (size_t)(300 + t) * 300;
            const float* wn = Whh + (size_t)(600 + t) * 300;
            float s1 = 0.f, s2 = 0.f, s3 = 0.f;
            for (int k = 0; k < 300; k++) {
                float h = et[k];
                s1 += wr[k] * h; s2 += wz[k] * h; s3 += wn[k] * h;
            }
            float ghr = s1 + bhh[t], ghz = s2 + bhh[300 + t], ghn = s3 + bhh[600 + t];
            float r = sigm(gir + ghr);
            float z = sigm(giz + ghz);
            float n = tanhf(gin + r * ghn);
            newet = (1.f - z) * n + z * et[t];
        }
        __syncthreads();
        if (t < 300) et[t] = newet;
        __syncthreads();
    }
    for (int c = 0; c < 3; c++) {
        red[t] = (t < 300) ? et[t] * dW[c * 300 + t] : 0.f;
        __syncthreads();
        if (t < 160) red[t] += red[t + 160]; __syncthreads();
        if (t < 80)  red[t] += red[t + 80];  __syncthreads();
        if (t < 40)  red[t] += red[t + 40];  __syncthreads();
        if (t < 20)  red[t] += red[t + 20];  __syncthreads();
        if (t < 10)  red[t] += red[t + 10];  __syncthreads();
        if (t < 5)   red[t] += red[t + 5];   __syncthreads();
        if (t == 0) {
            float s = red[0] + red[1] + red[2] + red[3] + red[4];
            outp[b * 3 + c] = s + db[c];
        }
        __syncthreads();
    }
}

// ---------------- launch -----------------------------------------------------
extern "C" void kernel_launch(void* const* d_in, const int* in_sizes, int n_in,
                              void* d_out, int out_size) {
    const int*   text      = (const int*)  d_in[0];
    const int*   aspect    = (const int*)  d_in[1];
    const int*   leftc     = (const int*)  d_in[2];
    const float* embedding = (const float*)d_in[3];
    const float* Wih_f     = (const float*)d_in[4];
    const float* Whh_f     = (const float*)d_in[5];
    const float* bih_f     = (const float*)d_in[6];
    const float* bhh_f     = (const float*)d_in[7];
    const float* Wih_b     = (const float*)d_in[8];
    const float* Whh_b     = (const float*)d_in[9];
    const float* bih_b     = (const float*)d_in[10];
    const float* bhh_b     = (const float*)d_in[11];
    const float* att_W     = (const float*)d_in[12];
    const float* gru_Wih   = (const float*)d_in[14];
    const float* gru_Whh   = (const float*)d_in[15];
    const float* gru_bih   = (const float*)d_in[16];
    const float* gru_bhh   = (const float*)d_in[17];
    const float* dense_W   = (const float*)d_in[18];
    const float* dense_b   = (const float*)d_in[19];
    float* outp = (float*)d_out;

    cudaFuncSetAttribute(k_scan8, cudaFuncAttributeMaxDynamicSharedMemorySize,
                         SC8_BYTES);

    k_prep<<<B_, 256>>>(text, aspect, leftc);
    k_sort<<<1, B_>>>();
    k_embed<<<B_ * S_, 96>>>(text, embedding);
    k_gemm<<<dim3(B_ * S_ / 128, (G4 + 127) / 128, 2), 256>>>(Wih_f, bih_f, Wih_b, bih_b);
    k_scan8<<<dim3(8, 32), 768, SC8_BYTES>>>(Whh_f, bhh_f, Whh_b, bhh_b);
    k_attn<<<B_, 256>>>(att_W);
    k_final<<<B_, 320>>>(gru_Wih, gru_Whh, gru_bih, gru_bhh, dense_W, dense_b, outp);
}

// round 6
// speedup vs baseline: 2.8183x; 1.0321x over previous
#include <cuda_runtime.h>
#include <math.h>
#include <stdint.h>

#define B_ 128
#define S_ 256
#define E_ 300
#define H_ 300
#define G4 1200   // 4*H
#define DIV 601   // 2H+1
#define NM 38     // h-slice per cluster CTA (8*38=304 >= 300)
#define KC 5      // k-chunks per row
#define CHF 60    // floats per chunk
#define HPAD2 304 // padded h stride
#define NB 8      // batches per cluster

// ---------------- scratch ----------------------------------------------------
__device__ float g_mem [B_*S_*E_];
__device__ float g_xgf [B_*S_*G4];
__device__ float g_xgb [B_*S_*G4];
__device__ float g_outf[B_*S_*H_];
__device__ float g_outb[B_*S_*H_];
__device__ float g_ivec[B_*DIV];
__device__ int   g_mlen[B_], g_llen[B_], g_alen[B_];
__device__ int   g_perm[B_];

__device__ __forceinline__ float sigm(float x) { return 1.f / (1.f + expf(-x)); }

__device__ __forceinline__ uint32_t smem_u32(const void* p) {
    uint32_t a;
    asm("{ .reg .u64 t; cvta.to.shared.u64 t, %1; cvt.u32.u64 %0, t; }" : "=r"(a) : "l"(p));
    return a;
}
__device__ __forceinline__ unsigned long long pack2(float a, float b) {
    unsigned long long r;
    asm("mov.b64 %0, {%1,%2};" : "=l"(r) : "f"(a), "f"(b));
    return r;
}
__device__ __forceinline__ void fma2(unsigned long long& acc,
                                     unsigned long long a, unsigned long long b) {
    asm("fma.rn.f32x2 %0, %1, %2, %0;" : "+l"(acc) : "l"(a), "l"(b));
}
__device__ __forceinline__ float2 unpack2(unsigned long long v) {
    float2 f;
    asm("mov.b64 {%0,%1}, %2;" : "=f"(f.x), "=f"(f.y) : "l"(v));
    return f;
}
__device__ __forceinline__ void lds2u64(unsigned long long& a, unsigned long long& b,
                                        uint32_t addr) {
    asm volatile("ld.shared.v2.b64 {%0,%1}, [%2];" : "=l"(a), "=l"(b) : "r"(addr));
}
__device__ __forceinline__ float warpred(float v) {
#pragma unroll
    for (int o = 16; o > 0; o >>= 1) v += __shfl_down_sync(0xffffffffu, v, o);
    return v;
}

// ---------------- K0: lengths ------------------------------------------------
__global__ void k_prep(const int* __restrict__ text,
                       const int* __restrict__ aspect,
                       const int* __restrict__ leftc) {
    int b = blockIdx.x, t = threadIdx.x;
    int c1 = __syncthreads_count(text[b*S_ + t] != 0);
    int c2 = __syncthreads_count(leftc[b*S_ + t] != 0);
    int c3 = __syncthreads_count(t < 8 && aspect[b*8 + t] != 0);
    if (t == 0) { g_mlen[b] = c1; g_llen[b] = c2; g_alen[b] = c3; }
}

// ---------------- K0b: sort batches by length --------------------------------
__global__ void k_sort() {
    __shared__ int v[B_];
    int t = threadIdx.x;
    v[t] = (g_mlen[t] << 8) | t;
    __syncthreads();
    for (int k = 2; k <= B_; k <<= 1) {
        for (int j = k >> 1; j > 0; j >>= 1) {
            int ixj = t ^ j;
            if (ixj > t) {
                int a = v[t], b = v[ixj];
                bool up = ((t & k) == 0);
                if ((a > b) == up) { v[t] = b; v[ixj] = a; }
            }
            __syncthreads();
        }
    }
    g_perm[t] = v[t] & 255;
}

// ---------------- K1: embedding gather ---------------------------------------
__global__ void k_embed(const int* __restrict__ text,
                        const float* __restrict__ emb) {
    int r = blockIdx.x;
    int id = text[r];
    const float4* src = (const float4*)(emb + (size_t)id * E_);
    float4* dst = (float4*)(g_mem + (size_t)r * E_);
    int t = threadIdx.x;
    if (t < 75) dst[t] = src[t];
}

// ---------------- K2: xg GEMM, double-buffered + reg prefetch ---------------
__global__ __launch_bounds__(256, 2) void k_gemm(
    const float* __restrict__ Wf, const float* __restrict__ bf,
    const float* __restrict__ Wb, const float* __restrict__ bb_) {
    const int N = G4, K = E_;
    const float* W    = blockIdx.z ? Wb  : Wf;
    const float* bias = blockIdx.z ? bb_ : bf;
    float* C          = blockIdx.z ? g_xgb : g_xgf;
    const float* A = g_mem;

    __shared__ __align__(16) float As[2][12][128];
    __shared__ __align__(16) float Bs[2][12][128];
    int tid = threadIdx.x;
    int tx = tid & 15, ty = tid >> 4;
    int m0 = blockIdx.x * 128, n0 = blockIdx.y * 128;

    // staging indices (idx0 = tid, idx1 = tid+256 when < 384)
    const int aM0 = tid / 3,        aX0 = tid % 3;
    const int i1  = tid + 256;
    const bool v1 = (i1 < 384);
    const int aM1 = v1 ? i1 / 3 : 0, aX1 = v1 ? i1 % 3 : 0;

    float4 rA0, rA1, rB0, rB1;

    auto ldTiles = [&](int kt) {
        int k0 = kt * 12;
        rA0 = *(const float4*)(A + (size_t)(m0 + aM0) * K + k0 + 4 * aX0);
        rA1 = v1 ? *(const float4*)(A + (size_t)(m0 + aM1) * K + k0 + 4 * aX1)
                 : make_float4(0.f,0.f,0.f,0.f);
        rB0 = (n0 + aM0 < N)
              ? *(const float4*)(W + (size_t)(n0 + aM0) * K + k0 + 4 * aX0)
              : make_float4(0.f,0.f,0.f,0.f);
        rB1 = (v1 && n0 + aM1 < N)
              ? *(const float4*)(W + (size_t)(n0 + aM1) * K + k0 + 4 * aX1)
              : make_float4(0.f,0.f,0.f,0.f);
    };
    auto stTiles = [&](int buf) {
        As[buf][4*aX0+0][aM0] = rA0.x; As[buf][4*aX0+1][aM0] = rA0.y;
        As[buf][4*aX0+2][aM0] = rA0.z; As[buf][4*aX0+3][aM0] = rA0.w;
        Bs[buf][4*aX0+0][aM0] = rB0.x; Bs[buf][4*aX0+1][aM0] = rB0.y;
        Bs[buf][4*aX0+2][aM0] = rB0.z; Bs[buf][4*aX0+3][aM0] = rB0.w;
        if (v1) {
            As[buf][4*aX1+0][aM1] = rA1.x; As[buf][4*aX1+1][aM1] = rA1.y;
            As[buf][4*aX1+2][aM1] = rA1.z; As[buf][4*aX1+3][aM1] = rA1.w;
            Bs[buf][4*aX1+0][aM1] = rB1.x; Bs[buf][4*aX1+1][aM1] = rB1.y;
            Bs[buf][4*aX1+2][aM1] = rB1.z; Bs[buf][4*aX1+3][aM1] = rB1.w;
        }
    };

    unsigned long long acc2[8][4];
#pragma unroll
    for (int i = 0; i < 8; i++)
#pragma unroll
        for (int j = 0; j < 4; j++) acc2[i][j] = 0ull;

    ldTiles(0);
    stTiles(0);
    __syncthreads();

    for (int kt = 0; kt < 25; kt++) {
        int cur = kt & 1;
        if (kt + 1 < 25) ldTiles(kt + 1);
#pragma unroll
        for (int k = 0; k < 12; k++) {
            float4 a1 = *(const float4*)&As[cur][k][ty*8];
            float4 a2 = *(const float4*)&As[cur][k][ty*8+4];
            float4 b1 = *(const float4*)&Bs[cur][k][tx*8];
            float4 b2 = *(const float4*)&Bs[cur][k][tx*8+4];
            unsigned long long bp[4] = {
                pack2(b1.x,b1.y), pack2(b1.z,b1.w),
                pack2(b2.x,b2.y), pack2(b2.z,b2.w) };
            float av[8] = {a1.x,a1.y,a1.z,a1.w,a2.x,a2.y,a2.z,a2.w};
#pragma unroll
            for (int i = 0; i < 8; i++) {
                unsigned long long ad = pack2(av[i], av[i]);
                fma2(acc2[i][0], ad, bp[0]);
                fma2(acc2[i][1], ad, bp[1]);
                fma2(acc2[i][2], ad, bp[2]);
                fma2(acc2[i][3], ad, bp[3]);
            }
        }
        if (kt + 1 < 25) stTiles(cur ^ 1);
        __syncthreads();
    }
#pragma unroll
    for (int i = 0; i < 8; i++) {
        int m = m0 + ty*8 + i;
#pragma unroll
        for (int jp = 0; jp < 4; jp++) {
            float2 v = unpack2(acc2[i][jp]);
            int n = n0 + tx*8 + 2*jp;
            if (n + 1 < N) {
                v.x += bias[n]; v.y += bias[n+1];
                *(float2*)(C + (size_t)m * N + n) = v;
            } else if (n < N) {
                C[(size_t)m * N + n] = v.x + bias[n];
            }
        }
    }
}

// ---------------- K3: clustered scan, 8 batches, weights in registers --------
#define SC8_FLOATS (2*NB*HPAD2 + NB*152 + 152*41 + 152)
#define SC8_BYTES  (SC8_FLOATS*4)

__global__ void __cluster_dims__(8,1,1) __launch_bounds__(768, 1)
k_scan8(const float* __restrict__ Whf, const float* __restrict__ bhf,
        const float* __restrict__ Whb, const float* __restrict__ bhb) {
    extern __shared__ float sm[];
    float* h_s   = sm;                        // [2][8][HPAD2]
    float* xg_s  = h_s + 2*NB*HPAD2;          // [8][152]
    float* g_s   = xg_s + NB*152;             // row*41 + bb*5 + kc
    float* bhh_s = g_s + 152*41;
    __shared__ int len_s[NB], bset[NB];
    __shared__ int maxlen_s;

    const int rank = blockIdx.x;
    const int grp  = blockIdx.y;              // 0..31: 16 fwd, 16 bwd
    const int dir  = grp >> 4;
    const int gi   = grp & 15;
    const int m0   = rank * NM;
    const int tid  = threadIdx.x;
    const bool act = tid < 760;
    const int kc   = act ? (tid / 152) : 0;
    const int row  = tid % 152;
    const int wm   = row >> 2, wg = row & 3;
    const bool wok = act && (m0 + wm < H_);

    const float* Whh = dir ? Whb : Whf;
    const float* bhh = dir ? bhb : bhf;
    const float* xg  = dir ? g_xgb : g_xgf;
    float* out       = dir ? g_outb : g_outf;

    if (tid < NB) {
        int b = g_perm[gi*NB + tid];
        bset[tid]  = b;
        len_s[tid] = g_mlen[b];
    }
    for (int i = tid; i < 2*NB*HPAD2; i += 768) h_s[i] = 0.f;
    if (tid < 152) {
        int m2 = tid >> 2, g2 = tid & 3;
        bhh_s[tid] = (m0 + m2 < H_) ? bhh[g2*300 + m0 + m2] : 0.f;
    }

    unsigned long long w2[30];
    {
        const float* wr = Whh + (size_t)(wg*300 + m0 + wm) * 300 + kc*CHF;
#pragma unroll
        for (int j = 0; j < 30; j++) {
            float2 v = make_float2(0.f, 0.f);
            if (wok) v = *(const float2*)(wr + 2*j);
            w2[j] = pack2(v.x, v.y);
        }
    }
    __syncthreads();
    if (tid == 0) {
        int mx = len_s[0];
        for (int i = 1; i < NB; i++) mx = max(mx, len_s[i]);
        maxlen_s = mx;
    }
    __syncthreads();
    const int maxlen = maxlen_s;

    asm volatile("barrier.cluster.arrive.aligned;" ::: "memory");
    asm volatile("barrier.cluster.wait.aligned;"   ::: "memory");

    const int p_bb0 = tid / 152;
    const int xcol  = wg*300 + m0 + wm;
    const bool xok  = (tid < 608) && (m0 + wm < H_);

    const int u_bb = tid & 7, u_m = tid >> 3;
    const bool uok = (tid < 304) && (m0 + u_m < H_);
    const int u_L  = len_s[u_bb & (NB-1)];
    const int u_b  = bset[u_bb & (NB-1)];
    const int mg   = m0 + u_m;
    float c_reg = 0.f;

    const uint32_t h_base = smem_u32(h_s);
    int buf = 0;
    for (int t = 0; t < maxlen; t++) {
        float xv0 = 0.f, xv1 = 0.f;
        if (xok) {
            int L0 = len_s[p_bb0], L1 = len_s[p_bb0 + 4];
            int s0 = dir ? (L0 - 1 - t) : t; if (s0 < 0) s0 = 0;
            int s1 = dir ? (L1 - 1 - t) : t; if (s1 < 0) s1 = 0;
            xv0 = xg[((size_t)bset[p_bb0    ]*S_ + s0)*G4 + xcol];
            xv1 = xg[((size_t)bset[p_bb0 + 4]*S_ + s1)*G4 + xcol];
        }
        if (act) {
#pragma unroll
            for (int p = 0; p < 2; p++) {
                unsigned long long a0 = 0ull, a1 = 0ull, a2 = 0ull, a3 = 0ull;
                uint32_t hb = h_base + (uint32_t)((buf*NB + 4*p)*HPAD2 + kc*CHF)*4u;
#pragma unroll
                for (int j = 0; j < 15; j++) {
                    unsigned long long q0, q1;
                    lds2u64(q0, q1, hb + j*16);
                    fma2(a0, w2[2*j], q0); fma2(a0, w2[2*j+1], q1);
                    lds2u64(q0, q1, hb + HPAD2*4 + j*16);
                    fma2(a1, w2[2*j], q0); fma2(a1, w2[2*j+1], q1);
                    lds2u64(q0, q1, hb + 2*HPAD2*4 + j*16);
                    fma2(a2, w2[2*j], q0); fma2(a2, w2[2*j+1], q1);
                    lds2u64(q0, q1, hb + 3*HPAD2*4 + j*16);
                    fma2(a3, w2[2*j], q0); fma2(a3, w2[2*j+1], q1);
                }
                float2 f0 = unpack2(a0), f1 = unpack2(a1);
                float2 f2 = unpack2(a2), f3 = unpack2(a3);
                g_s[row*41 + (4*p+0)*5 + kc] = f0.x + f0.y;
                g_s[row*41 + (4*p+1)*5 + kc] = f1.x + f1.y;
                g_s[row*41 + (4*p+2)*5 + kc] = f2.x + f2.y;
                g_s[row*41 + (4*p+3)*5 + kc] = f3.x + f3.y;
            }
        }
        if (tid < 608) {
            xg_s[p_bb0*152 + row]       = xv0;
            xg_s[(p_bb0 + 4)*152 + row] = xv1;
        }
        __syncthreads();
        if (uok) {
            float gv[4];
#pragma unroll
            for (int g = 0; g < 4; g++) {
                int r2 = u_m*4 + g;
                float s_ = xg_s[u_bb*152 + r2] + bhh_s[r2];
#pragma unroll
                for (int k2 = 0; k2 < KC; k2++) s_ += g_s[r2*41 + u_bb*5 + k2];
                gv[g] = s_;
            }
            float hw;
            if (t < u_L) {
                float ig = sigm(gv[0]), fg = sigm(gv[1]);
                float gt = tanhf(gv[2]), og = sigm(gv[3]);
                float cn = fg * c_reg + ig * gt;
                c_reg = cn;
                hw = og * tanhf(cn);
                int s = dir ? (u_L - 1 - t) : t;
                out[((size_t)u_b*S_ + s)*H_ + mg] = hw;
            } else {
                hw = h_s[(buf*NB + u_bb)*HPAD2 + mg];
                out[((size_t)u_b*S_ + t)*H_ + mg] = 0.f;
            }
            int nb2 = buf ^ 1;
            uint32_t laddr = smem_u32(&h_s[(nb2*NB + u_bb)*HPAD2 + mg]);
#pragma unroll
            for (int r = 0; r < 8; r++) {
                uint32_t raddr;
                asm volatile("mapa.shared::cluster.u32 %0, %1, %2;"
                             : "=r"(raddr) : "r"(laddr), "r"(r));
                asm volatile("st.shared::cluster.f32 [%0], %1;"
                             :: "r"(raddr), "f"(hw) : "memory");
            }
        }
        asm volatile("barrier.cluster.arrive.aligned;" ::: "memory");
        asm volatile("barrier.cluster.wait.aligned;"   ::: "memory");
        buf ^= 1;
    }
    for (int t = maxlen; t < S_; t++)
        if (uok)
            out[((size_t)u_b*S_ + t)*H_ + mg] = 0.f;
}

// ---------------- K4: attention ----------------------------------------------
__global__ __launch_bounds__(256) void k_attn(const float* __restrict__ attW) {
    __shared__ __align__(16) float attw_s[1204];
    __shared__ float aw_s[256];
    __shared__ float au_s[256];
    __shared__ float red[256];
    int b = blockIdx.x, t = threadIdx.x;
    for (int i = t; i < 1201; i += 256) attw_s[i] = attW[i];
    __syncthreads();

    float ml = (float)g_mlen[b], ll = (float)g_llen[b], al = (float)g_alen[b];
    float pos = (float)t;
    float w, u;
    if (pos < ll)                       { w = 1.f - (ll - pos) / ml;            u = pos - ll; }
    else if (pos >= ll + al && pos < ml){ w = 1.f - (pos - ll - al + 1.f) / ml; u = pos - ll - al + 1.f; }
    else                                { w = 1.f; u = 0.f; }

    const float4* rf = (const float4*)(g_outf + ((size_t)b * S_ + t) * H_);
    const float4* rb = (const float4*)(g_outb + ((size_t)b * S_ + t) * H_);
    float dot = 0.f;
#pragma unroll 5
    for (int k = 0; k < 75; k++) {
        float4 a = rf[k]; float4 wv = *(const float4*)&attw_s[4 * k];
        dot += a.x*wv.x + a.y*wv.y + a.z*wv.z + a.w*wv.w;
        float4 c = rb[k]; float4 wv2 = *(const float4*)&attw_s[300 + 4 * k];
        dot += c.x*wv2.x + c.y*wv2.y + c.z*wv2.z + c.w*wv2.w;
    }
    float score = w * dot + u * attw_s[600];

    red[t] = score; __syncthreads();
    for (int off = 128; off > 0; off >>= 1) {
        if (t < off) red[t] = fmaxf(red[t], red[t + off]);
        __syncthreads();
    }
    float mx = red[0]; __syncthreads();
    float e = expf(score - mx);
    red[t] = e; __syncthreads();
    for (int off = 128; off > 0; off >>= 1) {
        if (t < off) red[t] += red[t + off];
        __syncthreads();
    }
    float alpha = e / red[0];
    aw_s[t] = alpha * w;
    au_s[t] = alpha * u;
    __syncthreads();

    for (int d = t; d < DIV; d += 256) {
        float acc = 0.f;
        if (d < 300) {
            const float* p = g_outf + (size_t)b * S_ * H_ + d;
            for (int s = 0; s < S_; s++) acc += aw_s[s] * p[(size_t)s * H_];
        } else if (d < 600) {
            const float* p = g_outb + (size_t)b * S_ * H_ + (d - 300);
            for (int s = 0; s < S_; s++) acc += aw_s[s] * p[(size_t)s * H_];
        } else {
            for (int s = 0; s < S_; s++) acc += au_s[s];
        }
        g_ivec[b * DIV + d] = acc;
    }
}

// ---------------- K5: GRU hops + dense, coalesced warp-per-row GEMV ---------
__global__ __launch_bounds__(384) void k_final2(
    const float* __restrict__ Wih, const float* __restrict__ Whh,
    const float* __restrict__ bih, const float* __restrict__ bhh,
    const float* __restrict__ dW,  const float* __restrict__ db,
    float* __restrict__ outp) {
    __shared__ float iv_s[DIV];
    __shared__ float et_s[300];
    __shared__ float gi_s[900];
    __shared__ float gh_s[900];
    int b = blockIdx.x, t = threadIdx.x;
    int w = t >> 5, lane = t & 31;

    for (int i = t; i < DIV; i += 384) iv_s[i] = g_ivec[b * DIV + i];
    if (t < 300) et_s[t] = 0.f;
    __syncthreads();

    // gi[row] = Wih[row,:] . iv + bih[row]   (coalesced: lanes over k)
    for (int row = w; row < 900; row += 12) {
        const float* wp = Wih + (size_t)row * DIV;
        float acc = 0.f;
        for (int k = lane; k < DIV; k += 32) acc += wp[k] * iv_s[k];
        acc = warpred(acc);
        if (lane == 0) gi_s[row] = acc + bih[row];
    }
    __syncthreads();

    for (int hop = 0; hop < 3; hop++) {
        for (int row = w; row < 900; row += 12) {
            const float* wp = Whh + (size_t)row * 300;
            float acc = 0.f;
#pragma unroll 2
            for (int k = lane; k < 300; k += 32) acc += wp[k] * et_s[k];
            acc = warpred(acc);
            if (lane == 0) gh_s[row] = acc + bhh[row];
        }
        __syncthreads();
        float newet = 0.f;
        if (t < 300) {
            float r = sigm(gi_s[t]       + gh_s[t]);
            float z = sigm(gi_s[300 + t] + gh_s[300 + t]);
            float n = tanhf(gi_s[600 + t] + r * gh_s[600 + t]);
            newet = (1.f - z) * n + z * et_s[t];
        }
        __syncthreads();
        if (t < 300) et_s[t] = newet;
        __syncthreads();
    }

    if (w < 3) {
        const float* wp = dW + w * 300;
        float acc = 0.f;
        for (int k = lane; k < 300; k += 32) acc += wp[k] * et_s[k];
        acc = warpred(acc);
        if (lane == 0) outp[b * 3 + w] = acc + db[w];
    }
}

// ---------------- launch -----------------------------------------------------
extern "C" void kernel_launch(void* const* d_in, const int* in_sizes, int n_in,
                              void* d_out, int out_size) {
    const int*   text      = (const int*)  d_in[0];
    const int*   aspect    = (const int*)  d_in[1];
    const int*   leftc     = (const int*)  d_in[2];
    const float* embedding = (const float*)d_in[3];
    const float* Wih_f     = (const float*)d_in[4];
    const float* Whh_f     = (const float*)d_in[5];
    const float* bih_f     = (const float*)d_in[6];
    const float* bhh_f     = (const float*)d_in[7];
    const float* Wih_b     = (const float*)d_in[8];
    const float* Whh_b     = (const float*)d_in[9];
    const float* bih_b     = (const float*)d_in[10];
    const float* bhh_b     = (const float*)d_in[11];
    const float* att_W     = (const float*)d_in[12];
    const float* gru_Wih   = (const float*)d_in[14];
    const float* gru_Whh   = (const float*)d_in[15];
    const float* gru_bih   = (const float*)d_in[16];
    const float* gru_bhh   = (const float*)d_in[17];
    const float* dense_W   = (const float*)d_in[18];
    const float* dense_b   = (const float*)d_in[19];
    float* outp = (float*)d_out;

    cudaFuncSetAttribute(k_scan8, cudaFuncAttributeMaxDynamicSharedMemorySize,
                         SC8_BYTES);

    k_prep<<<B_, 256>>>(text, aspect, leftc);
    k_sort<<<1, B_>>>();
    k_embed<<<B_ * S_, 96>>>(text, embedding);
    k_gemm<<<dim3(B_ * S_ / 128, (G4 + 127) / 128, 2), 256>>>(Wih_f, bih_f, Wih_b, bih_b);
    k_scan8<<<dim3(8, 32), 768, SC8_BYTES>>>(Whh_f, bhh_f, Whh_b, bhh_b);
    k_attn<<<B_, 256>>>(att_W);
    k_final2<<<B_, 384>>>(gru_Wih, gru_Whh, gru_bih, gru_bhh, dense_W, dense_b, outp);
}